// round 8
// baseline (speedup 1.0000x reference)
#include <cuda_runtime.h>
#include <math.h>
#include <stdint.h>

// ---------------------------------------------------------------------------
// Problem constants
// ---------------------------------------------------------------------------
#define BB 8
#define NN_ 4096
#define MM_ 1024
#define DD 1024
#define HH 16
#define SCALE_F 0.125f
#define EPS_F 1e-6f
#define ROWS_X (BB * NN_)   // 32768
#define ROWS_W (BB * MM_)   // 8192

// int8 quantization scales (static, distribution-derived, clamp-guarded)
#define S_LN   (8.0f / 16384.0f)      // ln2 output, |z| <~ 6
#define S_HH   (6.0f / 16384.0f)      // silu(h), max ~3.9
#define S_WW   (0.125f / 16384.0f)    // weights 0.02*N(0,1), max ~0.11
#define QMUL_LN (16384.0f / 8.0f)
#define QMUL_H  (16384.0f / 6.0f)
#define QMUL_W  (16384.0f / 0.125f)

// ---------------------------------------------------------------------------
// Scratch (static device globals)
// ---------------------------------------------------------------------------
__device__ float g_bufA[(size_t)ROWS_W * DD];    // lnw
__device__ float g_buf1[(size_t)ROWS_X * DD];    // ln1 -> attn_out
__device__ float g_buf2[(size_t)ROWS_X * DD];    // q
__device__ float g_buf3[(size_t)ROWS_X * DD];    // x2
__device__ float g_kv[(size_t)ROWS_W * 2048];
__device__ float g_ctx[(size_t)BB * HH * 64 * 64];
// tf32 transposed weights (attention path)
__device__ float g_WqT[(size_t)1024 * 1024];
__device__ float g_WkvT[(size_t)2048 * 1024];
__device__ float g_WoT[(size_t)1024 * 1024];
// int8 dual-plane FFN tensors
__device__ int8_t g_W1hT[(size_t)4096 * 1024];
__device__ int8_t g_W1lT[(size_t)4096 * 1024];
__device__ int8_t g_W2hT[(size_t)1024 * 4096];
__device__ int8_t g_W2lT[(size_t)1024 * 4096];
__device__ int8_t g_lnH[(size_t)ROWS_X * 1024];
__device__ int8_t g_lnL[(size_t)ROWS_X * 1024];
__device__ int8_t g_hH[(size_t)ROWS_X * 4096];
__device__ int8_t g_hL[(size_t)ROWS_X * 4096];

// ---------------------------------------------------------------------------
// Helpers
// ---------------------------------------------------------------------------
__device__ __forceinline__ uint32_t smem_u32(const void* p) {
    uint32_t a;
    asm("{ .reg .u64 t; cvta.to.shared.u64 t, %1; cvt.u32.u64 %0, t; }"
        : "=r"(a) : "l"(p));
    return a;
}

__device__ __forceinline__ float to_tf32(float x) {
    uint32_t u;
    asm("cvt.rna.tf32.f32 %0, %1;" : "=r"(u) : "f"(x));
    return __uint_as_float(u);
}

__device__ __forceinline__ void cp_async16(uint32_t smem, const void* gmem) {
    asm volatile("cp.async.cg.shared.global [%0], [%1], 16;\n"
                 :: "r"(smem), "l"(gmem));
}
#define CP_COMMIT() asm volatile("cp.async.commit_group;" ::: "memory")

__device__ __forceinline__ uint32_t lds32(uint32_t addr) {
    uint32_t v;
    asm volatile("ld.shared.b32 %0, [%1];" : "=r"(v) : "r"(addr));
    return v;
}

__device__ __forceinline__ void mma_tf32(float* d, const uint32_t* a,
                                         const uint32_t* b) {
    asm volatile(
        "mma.sync.aligned.m16n8k8.row.col.f32.tf32.tf32.f32 "
        "{%0,%1,%2,%3}, {%4,%5,%6,%7}, {%8,%9}, {%0,%1,%2,%3};"
        : "+f"(d[0]), "+f"(d[1]), "+f"(d[2]), "+f"(d[3])
        : "r"(a[0]), "r"(a[1]), "r"(a[2]), "r"(a[3]), "r"(b[0]), "r"(b[1]));
}

__device__ __forceinline__ void mma_s8(int* d, const uint32_t* a,
                                       const uint32_t* b) {
    asm volatile(
        "mma.sync.aligned.m16n8k32.row.col.s32.s8.s8.s32 "
        "{%0,%1,%2,%3}, {%4,%5,%6,%7}, {%8,%9}, {%0,%1,%2,%3};"
        : "+r"(d[0]), "+r"(d[1]), "+r"(d[2]), "+r"(d[3])
        : "r"(a[0]), "r"(a[1]), "r"(a[2]), "r"(a[3]), "r"(b[0]), "r"(b[1]));
}

// split 15-bit value: x -> (h, l) with x ~= (h*128 + l)
__device__ __forceinline__ void q15_split(float v, float qmul, int& h, int& l) {
    int X = __float2int_rn(v * qmul);
    X = max(-16256, min(16256, X));
    h = (X + 64) >> 7;
    l = X - (h << 7);
}

// smem fragment address (fp32 tf32 path): 128B rows, XOR swizzle on 16B units
__device__ __forceinline__ uint32_t fragoff(int r, int c) {
    return (uint32_t)(r * 128 + (((c >> 2) ^ (r & 7)) << 4) + ((c & 3) << 2));
}

// ---------------------------------------------------------------------------
// tf32 mma.sync GEMM (attention path): C = A @ BT^T + bias (+res)
// CTA 256x128, 8 warps (4x2), warp tile 64x64, K-chunk 32, 3-stage cp.async
// EP: 0 = +bias ; 1 = +bias +res
// ---------------------------------------------------------------------------
#define A_STAGE_BYTES 32768u
#define B_STAGE_BYTES 16384u
#define STAGE_BYTES (A_STAGE_BYTES + B_STAGE_BYTES)
#define NSTAGE 3
#define DSMEM_BYTES (NSTAGE * STAGE_BYTES)

template <int EP>
__global__ void __launch_bounds__(256)
tgemm(const float* __restrict__ A, const float* __restrict__ BT,
      const float* __restrict__ bias, const float* __restrict__ res,
      float* __restrict__ C, int Ncols, int K) {
    extern __shared__ char dsm[];
    const uint32_t smem0 = smem_u32(dsm);

    const int tid = threadIdx.x;
    const int lane = tid & 31, warp = tid >> 5;
    const int wy = warp >> 1, wx = warp & 1;
    const int gid = lane >> 2, tig = lane & 3;
    const int bm = blockIdx.y, bn = blockIdx.x;

    const float* Abase = A + (size_t)(bm * 256) * K;
    const float* Bbase = BT + (size_t)(bn * 128) * K;
    const int ntiles = K >> 5;

    float acc[4][8][4];
    #pragma unroll
    for (int mt = 0; mt < 4; mt++)
        #pragma unroll
        for (int nt = 0; nt < 8; nt++)
            #pragma unroll
            for (int r = 0; r < 4; r++) acc[mt][nt][r] = 0.f;

    auto load_chunk = [&](int c) {
        const uint32_t so = smem0 + (uint32_t)(c % NSTAGE) * STAGE_BYTES;
        const int k0 = c << 5;
        #pragma unroll
        for (int t = 0; t < 8; t++) {
            const int i = tid + t * 256;
            const int r = i >> 3, u = i & 7;
            const uint32_t du = (uint32_t)((u ^ (r & 7)) << 4);
            cp_async16(so + (uint32_t)(r * 128) + du,
                       Abase + (size_t)r * K + k0 + u * 4);
        }
        #pragma unroll
        for (int t = 0; t < 4; t++) {
            const int i = tid + t * 256;
            const int r = i >> 3, u = i & 7;
            const uint32_t du = (uint32_t)((u ^ (r & 7)) << 4);
            cp_async16(so + A_STAGE_BYTES + (uint32_t)(r * 128) + du,
                       Bbase + (size_t)r * K + k0 + u * 4);
        }
        CP_COMMIT();
    };

    load_chunk(0);
    load_chunk(1);

    for (int c = 0; c < ntiles; c++) {
        asm volatile("cp.async.wait_group 1;" ::: "memory");
        __syncthreads();
        if (c + 2 < ntiles) load_chunk(c + 2);
        else CP_COMMIT();

        const uint32_t sA = smem0 + (uint32_t)(c % NSTAGE) * STAGE_BYTES;
        const uint32_t sB = sA + A_STAGE_BYTES;

        #pragma unroll
        for (int ks = 0; ks < 4; ks++) {
            const int kc = ks * 8 + tig;
            uint32_t a[4][4];
            #pragma unroll
            for (int mt = 0; mt < 4; mt++) {
                const int r0 = wy * 64 + mt * 16 + gid;
                a[mt][0] = lds32(sA + fragoff(r0,     kc));
                a[mt][1] = lds32(sA + fragoff(r0 + 8, kc));
                a[mt][2] = lds32(sA + fragoff(r0,     kc + 4));
                a[mt][3] = lds32(sA + fragoff(r0 + 8, kc + 4));
            }
            #pragma unroll
            for (int nt = 0; nt < 8; nt++) {
                const int n0 = wx * 64 + nt * 8 + gid;
                uint32_t b[2];
                b[0] = lds32(sB + fragoff(n0, kc));
                b[1] = lds32(sB + fragoff(n0, kc + 4));
                #pragma unroll
                for (int mt = 0; mt < 4; mt++)
                    mma_tf32(acc[mt][nt], a[mt], b);
            }
        }
        __syncthreads();
    }

    #pragma unroll
    for (int mt = 0; mt < 4; mt++) {
        const int r0 = bm * 256 + wy * 64 + mt * 16 + gid;
        #pragma unroll
        for (int nt = 0; nt < 8; nt++) {
            const int col = bn * 128 + wx * 64 + nt * 8 + tig * 2;
            float2 b2 = *(const float2*)(bias + col);
            float v0 = acc[mt][nt][0] + b2.x;
            float v1 = acc[mt][nt][1] + b2.y;
            float v2 = acc[mt][nt][2] + b2.x;
            float v3 = acc[mt][nt][3] + b2.y;
            if (EP == 1) {
                float2 ra = *(const float2*)(res + (size_t)r0 * Ncols + col);
                float2 rb = *(const float2*)(res + (size_t)(r0 + 8) * Ncols + col);
                v0 += ra.x; v1 += ra.y; v2 += rb.x; v3 += rb.y;
            }
            *(float2*)(C + (size_t)r0 * Ncols + col)       = make_float2(v0, v1);
            *(float2*)(C + (size_t)(r0 + 8) * Ncols + col) = make_float2(v2, v3);
        }
    }
}

// ---------------------------------------------------------------------------
// int8 dual-plane GEMM (FFN): C = (Ah,Al) @ (Bh,Bl)^T combined
// CTA 128x64, 4 warps (2x2), warp tile 64x32, K-chunk 64 (2 x k32 MMA steps),
// 3-stage cp.async, dual s32 accumulators (hh, hl+lh).
// smem layout per stage: A: [plane][k16-unit 0..3][128 rows][16B] (16KB)
//                        B: [plane][k16-unit 0..3][64 rows][16B]  (8KB)
// EP: 0 = silu(+bias) -> requantized int8 planes ; 1 = +bias +res -> fp32
// ---------------------------------------------------------------------------
#define I8_STAGE 24576u
#define I8_NSTAGE 3
#define I8_DSMEM (I8_NSTAGE * I8_STAGE)

template <int EP>
__global__ void __launch_bounds__(128, 2)
i8gemm(const int8_t* __restrict__ Ah, const int8_t* __restrict__ Al,
       const int8_t* __restrict__ Bh, const int8_t* __restrict__ Bl,
       const float* __restrict__ bias, const float* __restrict__ res,
       float* __restrict__ outF, int8_t* __restrict__ outH,
       int8_t* __restrict__ outL, int Ncols, int K,
       float c16k, float c128, float qmul) {
    extern __shared__ char dsm[];
    const uint32_t smem0 = smem_u32(dsm);

    const int tid = threadIdx.x;
    const int lane = tid & 31, warp = tid >> 5;
    const int wy = warp >> 1, wx = warp & 1;    // warp tile 64 rows x 32 cols
    const int gid = lane >> 2, tig = lane & 3;
    const int bm = blockIdx.y, bn = blockIdx.x;

    const int8_t* AhB = Ah + (size_t)(bm * 128) * K;
    const int8_t* AlB = Al + (size_t)(bm * 128) * K;
    const int8_t* BhB = Bh + (size_t)(bn * 64) * K;
    const int8_t* BlB = Bl + (size_t)(bn * 64) * K;
    const int ntiles = K >> 6;

    int acc1[4][4][4];   // hi*hi
    int acc2[4][4][4];   // hi*lo + lo*hi
    #pragma unroll
    for (int mt = 0; mt < 4; mt++)
        #pragma unroll
        for (int nt = 0; nt < 4; nt++)
            #pragma unroll
            for (int r = 0; r < 4; r++) { acc1[mt][nt][r] = 0; acc2[mt][nt][r] = 0; }

    auto load_chunk = [&](int c) {
        const uint32_t so = smem0 + (uint32_t)(c % I8_NSTAGE) * I8_STAGE;
        const int k0 = c << 6;
        // A: 1024 16B units (2 planes x 4 units x 128 rows)
        #pragma unroll
        for (int t = 0; t < 8; t++) {
            const int i = tid + t * 128;
            const int pl = i >> 9, rem = i & 511;
            const int j = rem >> 7, r = rem & 127;
            const int8_t* g = (pl ? AlB : AhB) + (size_t)r * K + k0 + j * 16;
            cp_async16(so + (uint32_t)(pl * 8192 + j * 2048 + r * 16), g);
        }
        // B: 512 16B units (2 planes x 4 units x 64 rows)
        #pragma unroll
        for (int t = 0; t < 4; t++) {
            const int i = tid + t * 128;
            const int pl = i >> 8, rem = i & 255;
            const int j = rem >> 6, r = rem & 63;
            const int8_t* g = (pl ? BlB : BhB) + (size_t)r * K + k0 + j * 16;
            cp_async16(so + 16384u + (uint32_t)(pl * 4096 + j * 1024 + r * 16), g);
        }
        CP_COMMIT();
    };

    load_chunk(0);
    load_chunk(1);

    for (int c = 0; c < ntiles; c++) {
        asm volatile("cp.async.wait_group 1;" ::: "memory");
        __syncthreads();
        if (c + 2 < ntiles) load_chunk(c + 2);
        else CP_COMMIT();

        const uint32_t so = smem0 + (uint32_t)(c % I8_NSTAGE) * I8_STAGE;
        const uint32_t sB = so + 16384u;

        #pragma unroll
        for (int s = 0; s < 2; s++) {
            const uint32_t u0 = (uint32_t)(2 * s) * 2048u;       // A unit offset
            const uint32_t v0 = (uint32_t)(2 * s) * 1024u;       // B unit offset
            uint32_t ah[4][4], al[4][4];
            #pragma unroll
            for (int mt = 0; mt < 4; mt++) {
                const uint32_t r0 = (uint32_t)((wy * 64 + mt * 16 + gid) * 16 + 4 * tig);
                const uint32_t r8 = r0 + 128u;                   // +8 rows * 16B
                ah[mt][0] = lds32(so + u0 + r0);
                ah[mt][1] = lds32(so + u0 + r8);
                ah[mt][2] = lds32(so + u0 + 2048u + r0);
                ah[mt][3] = lds32(so + u0 + 2048u + r8);
                al[mt][0] = lds32(so + 8192u + u0 + r0);
                al[mt][1] = lds32(so + 8192u + u0 + r8);
                al[mt][2] = lds32(so + 8192u + u0 + 2048u + r0);
                al[mt][3] = lds32(so + 8192u + u0 + 2048u + r8);
            }
            uint32_t bh[4][2], bl[4][2];
            #pragma unroll
            for (int nt = 0; nt < 4; nt++) {
                const uint32_t n0 = (uint32_t)((wx * 32 + nt * 8 + gid) * 16 + 4 * tig);
                bh[nt][0] = lds32(sB + v0 + n0);
                bh[nt][1] = lds32(sB + v0 + 1024u + n0);
                bl[nt][0] = lds32(sB + 4096u + v0 + n0);
                bl[nt][1] = lds32(sB + 4096u + v0 + 1024u + n0);
            }
            #pragma unroll
            for (int nt = 0; nt < 4; nt++)
                #pragma unroll
                for (int mt = 0; mt < 4; mt++) {
                    mma_s8(acc1[mt][nt], ah[mt], bh[nt]);
                    mma_s8(acc2[mt][nt], ah[mt], bl[nt]);
                    mma_s8(acc2[mt][nt], al[mt], bh[nt]);
                }
        }
        __syncthreads();
    }

    // epilogue
    #pragma unroll
    for (int mt = 0; mt < 4; mt++) {
        const int r0 = bm * 128 + wy * 64 + mt * 16 + gid;
        #pragma unroll
        for (int nt = 0; nt < 4; nt++) {
            const int col = bn * 64 + wx * 32 + nt * 8 + tig * 2;
            float2 b2 = *(const float2*)(bias + col);
            float v0 = c16k * (float)acc1[mt][nt][0] + c128 * (float)acc2[mt][nt][0] + b2.x;
            float v1 = c16k * (float)acc1[mt][nt][1] + c128 * (float)acc2[mt][nt][1] + b2.y;
            float v2 = c16k * (float)acc1[mt][nt][2] + c128 * (float)acc2[mt][nt][2] + b2.x;
            float v3 = c16k * (float)acc1[mt][nt][3] + c128 * (float)acc2[mt][nt][3] + b2.y;
            if (EP == 1) {
                float2 ra = *(const float2*)(res + (size_t)r0 * Ncols + col);
                float2 rb = *(const float2*)(res + (size_t)(r0 + 8) * Ncols + col);
                v0 += ra.x; v1 += ra.y; v2 += rb.x; v3 += rb.y;
                *(float2*)(outF + (size_t)r0 * Ncols + col)       = make_float2(v0, v1);
                *(float2*)(outF + (size_t)(r0 + 8) * Ncols + col) = make_float2(v2, v3);
            } else {
                v0 = v0 * (1.f / (1.f + __expf(-v0)));
                v1 = v1 * (1.f / (1.f + __expf(-v1)));
                v2 = v2 * (1.f / (1.f + __expf(-v2)));
                v3 = v3 * (1.f / (1.f + __expf(-v3)));
                int h0, l0, h1, l1;
                q15_split(v0, qmul, h0, l0);
                q15_split(v1, qmul, h1, l1);
                uchar2 hh0 = make_uchar2((unsigned char)(signed char)h0,
                                         (unsigned char)(signed char)h1);
                uchar2 ll0 = make_uchar2((unsigned char)(signed char)l0,
                                         (unsigned char)(signed char)l1);
                *(uchar2*)(outH + (size_t)r0 * Ncols + col) = hh0;
                *(uchar2*)(outL + (size_t)r0 * Ncols + col) = ll0;
                q15_split(v2, qmul, h0, l0);
                q15_split(v3, qmul, h1, l1);
                uchar2 hh1 = make_uchar2((unsigned char)(signed char)h0,
                                         (unsigned char)(signed char)h1);
                uchar2 ll1 = make_uchar2((unsigned char)(signed char)l0,
                                         (unsigned char)(signed char)l1);
                *(uchar2*)(outH + (size_t)(r0 + 8) * Ncols + col) = hh1;
                *(uchar2*)(outL + (size_t)(r0 + 8) * Ncols + col) = ll1;
            }
        }
    }
}

// ---------------------------------------------------------------------------
// Weight transpose variants
// ---------------------------------------------------------------------------
__global__ void transpose_tf32(const float* __restrict__ in, float* __restrict__ out,
                               int K, int N) {
    __shared__ float t[32][33];
    const int bx = blockIdx.x * 32, by = blockIdx.y * 32;
    const int x = threadIdx.x, y = threadIdx.y;
    #pragma unroll
    for (int i = 0; i < 32; i += 8)
        t[y + i][x] = in[(size_t)(by + y + i) * N + bx + x];
    __syncthreads();
    #pragma unroll
    for (int i = 0; i < 32; i += 8)
        out[(size_t)(bx + y + i) * K + by + x] = to_tf32(t[x][y + i]);
}

__global__ void transpose_q8(const float* __restrict__ in, int8_t* __restrict__ oh,
                             int8_t* __restrict__ ol, int K, int N) {
    __shared__ float t[32][33];
    const int bx = blockIdx.x * 32, by = blockIdx.y * 32;
    const int x = threadIdx.x, y = threadIdx.y;
    #pragma unroll
    for (int i = 0; i < 32; i += 8)
        t[y + i][x] = in[(size_t)(by + y + i) * N + bx + x];
    __syncthreads();
    #pragma unroll
    for (int i = 0; i < 32; i += 8) {
        int h, l;
        q15_split(t[x][y + i], QMUL_W, h, l);
        oh[(size_t)(bx + y + i) * K + by + x] = (int8_t)h;
        ol[(size_t)(bx + y + i) * K + by + x] = (int8_t)l;
    }
}

// ---------------------------------------------------------------------------
// LayerNorm: fp32/tf32 output (attention) and int8-plane output (FFN)
// ---------------------------------------------------------------------------
template <int Q8>
__global__ void ln_kernel_t(const float* __restrict__ x, const float* __restrict__ g,
                            const float* __restrict__ bta, float* __restrict__ y,
                            int8_t* __restrict__ oh, int8_t* __restrict__ ol) {
    const int tid = threadIdx.x;
    const size_t row = blockIdx.x;
    float4 v = ((const float4*)(x + row * DD))[tid];
    __shared__ float red[32];

    float s = v.x + v.y + v.z + v.w;
    #pragma unroll
    for (int o = 16; o; o >>= 1) s += __shfl_xor_sync(0xffffffffu, s, o);
    if ((tid & 31) == 0) red[tid >> 5] = s;
    __syncthreads();
    if (tid < 32) {
        float t = (tid < 8) ? red[tid] : 0.f;
        #pragma unroll
        for (int o = 4; o; o >>= 1) t += __shfl_xor_sync(0xffffffffu, t, o);
        if (tid == 0) red[0] = t;
    }
    __syncthreads();
    const float mean = red[0] * (1.f / DD);

    float dx = v.x - mean, dy = v.y - mean, dz = v.z - mean, dw = v.w - mean;
    float ss = dx * dx + dy * dy + dz * dz + dw * dw;
    #pragma unroll
    for (int o = 16; o; o >>= 1) ss += __shfl_xor_sync(0xffffffffu, ss, o);
    __syncthreads();
    if ((tid & 31) == 0) red[tid >> 5] = ss;
    __syncthreads();
    if (tid < 32) {
        float t = (tid < 8) ? red[tid] : 0.f;
        #pragma unroll
        for (int o = 4; o; o >>= 1) t += __shfl_xor_sync(0xffffffffu, t, o);
        if (tid == 0) red[0] = t;
    }
    __syncthreads();
    const float rstd = rsqrtf(red[0] * (1.f / DD) + EPS_F);

    float4 gg = ((const float4*)g)[tid];
    float4 bb = ((const float4*)bta)[tid];
    float o0 = dx * rstd * gg.x + bb.x;
    float o1 = dy * rstd * gg.y + bb.y;
    float o2 = dz * rstd * gg.z + bb.z;
    float o3 = dw * rstd * gg.w + bb.w;
    if (Q8) {
        int h0, l0, h1, l1, h2, l2, h3, l3;
        q15_split(o0, QMUL_LN, h0, l0);
        q15_split(o1, QMUL_LN, h1, l1);
        q15_split(o2, QMUL_LN, h2, l2);
        q15_split(o3, QMUL_LN, h3, l3);
        uint32_t hp = (uint32_t)(uint8_t)(int8_t)h0 |
                      ((uint32_t)(uint8_t)(int8_t)h1 << 8) |
                      ((uint32_t)(uint8_t)(int8_t)h2 << 16) |
                      ((uint32_t)(uint8_t)(int8_t)h3 << 24);
        uint32_t lp = (uint32_t)(uint8_t)(int8_t)l0 |
                      ((uint32_t)(uint8_t)(int8_t)l1 << 8) |
                      ((uint32_t)(uint8_t)(int8_t)l2 << 16) |
                      ((uint32_t)(uint8_t)(int8_t)l3 << 24);
        ((uint32_t*)(oh + row * DD))[tid] = hp;
        ((uint32_t*)(ol + row * DD))[tid] = lp;
    } else {
        float4 o4;
        o4.x = to_tf32(o0); o4.y = to_tf32(o1);
        o4.z = to_tf32(o2); o4.w = to_tf32(o3);
        ((float4*)(y + row * DD))[tid] = o4;
    }
}

// ---------------------------------------------------------------------------
// softmax over N axis of q[B,N,D] per (b, channel)
// ---------------------------------------------------------------------------
__global__ void softmax_q_kernel(float* __restrict__ q) {
    const int b = blockIdx.y;
    const int c = (blockIdx.x << 5) + threadIdx.x;
    const int ty = threadIdx.y;
    float* base = q + (size_t)b * NN_ * DD + c;

    float m = -1e30f, s = 0.f;
    for (int n = ty; n < NN_; n += 8) {
        float v = base[(size_t)n * DD];
        if (v > m) { s = s * __expf(m - v) + 1.f; m = v; }
        else       { s += __expf(v - m); }
    }
    __shared__ float sm[8][32], ssum[8][32];
    sm[ty][threadIdx.x] = m; ssum[ty][threadIdx.x] = s;
    __syncthreads();
    float Mv = -1e30f;
    #pragma unroll
    for (int i = 0; i < 8; i++) Mv = fmaxf(Mv, sm[i][threadIdx.x]);
    float Sv = 0.f;
    #pragma unroll
    for (int i = 0; i < 8; i++) Sv += ssum[i][threadIdx.x] * __expf(sm[i][threadIdx.x] - Mv);
    const float inv = 1.f / Sv;
    for (int n = ty; n < NN_; n += 8) {
        float v = base[(size_t)n * DD];
        base[(size_t)n * DD] = __expf(v - Mv) * inv;
    }
}

__global__ void softmax_k_kernel(float* __restrict__ kv) {
    const size_t row = blockIdx.x;
    const int w = threadIdx.x >> 5, lane = threadIdx.x & 31;
    float* p = kv + row * 2048 + w * 64;
    float a = p[lane], c = p[lane + 32];
    float m = fmaxf(a, c);
    #pragma unroll
    for (int o = 16; o; o >>= 1) m = fmaxf(m, __shfl_xor_sync(0xffffffffu, m, o));
    float ea = __expf(a - m), ec = __expf(c - m);
    float s = ea + ec;
    #pragma unroll
    for (int o = 16; o; o >>= 1) s += __shfl_xor_sync(0xffffffffu, s, o);
    const float inv = 1.f / s;
    p[lane] = ea * inv; p[lane + 32] = ec * inv;
}

__global__ void context_kernel(const float* __restrict__ kv, float* __restrict__ ctx) {
    const int bh = blockIdx.x;
    const int b = bh >> 4, h = bh & 15;
    __shared__ float Ks[64][64];
    __shared__ float Vs[64][64];
    const int tid = threadIdx.x;
    const int tx = tid & 15, ty = tid >> 4;
    const float* kvb = kv + (size_t)b * MM_ * 2048 + h * 64;

    float acc[4][4];
    #pragma unroll
    for (int i = 0; i < 4; i++)
        #pragma unroll
        for (int j = 0; j < 4; j++) acc[i][j] = 0.f;

    for (int m0 = 0; m0 < MM_; m0 += 64) {
        for (int i = tid; i < 1024; i += 256) {
            int r = i >> 4, c4 = (i & 15) << 2;
            const float* rp = kvb + (size_t)(m0 + r) * 2048 + c4;
            *(float4*)&Ks[r][c4] = *(const float4*)rp;
            *(float4*)&Vs[r][c4] = *(const float4*)(rp + 1024);
        }
        __syncthreads();
        #pragma unroll 8
        for (int mm = 0; mm < 64; mm++) {
            float a0 = Ks[mm][ty * 4 + 0], a1 = Ks[mm][ty * 4 + 1];
            float a2 = Ks[mm][ty * 4 + 2], a3 = Ks[mm][ty * 4 + 3];
            float b0 = Vs[mm][tx * 4 + 0], b1 = Vs[mm][tx * 4 + 1];
            float b2 = Vs[mm][tx * 4 + 2], b3 = Vs[mm][tx * 4 + 3];
            acc[0][0] += a0 * b0; acc[0][1] += a0 * b1; acc[0][2] += a0 * b2; acc[0][3] += a0 * b3;
            acc[1][0] += a1 * b0; acc[1][1] += a1 * b1; acc[1][2] += a1 * b2; acc[1][3] += a1 * b3;
            acc[2][0] += a2 * b0; acc[2][1] += a2 * b1; acc[2][2] += a2 * b2; acc[2][3] += a2 * b3;
            acc[3][0] += a3 * b0; acc[3][1] += a3 * b1; acc[3][2] += a3 * b2; acc[3][3] += a3 * b3;
        }
        __syncthreads();
    }
    float* cb = ctx + (size_t)bh * 64 * 64;
    #pragma unroll
    for (int i = 0; i < 4; i++) {
        float o[4];
        #pragma unroll
        for (int j = 0; j < 4; j++) o[j] = acc[i][j] * SCALE_F;
        *(float4*)(cb + (ty * 4 + i) * 64 + tx * 4) = *(float4*)&o[0];
    }
}

__global__ void apply_ctx_kernel(const float* __restrict__ q, const float* __restrict__ ctx,
                                 float* __restrict__ outp) {
    const int bh = blockIdx.y;
    const int b = bh >> 4, h = bh & 15;
    const int n0 = blockIdx.x << 6;
    __shared__ float Cs[64][64];
    __shared__ float Qs[64][64];
    const int tid = threadIdx.x;
    const float* qb = q + ((size_t)(b * NN_ + n0)) * DD + h * 64;
    const float* cb = ctx + (size_t)bh * 64 * 64;

    for (int i = tid; i < 1024; i += 256) {
        int r = i >> 4, c4 = (i & 15) << 2;
        *(float4*)&Cs[r][c4] = *(const float4*)(cb + r * 64 + c4);
        *(float4*)&Qs[r][c4] = *(const float4*)(qb + (size_t)r * DD + c4);
    }
    __syncthreads();

    const int tx = tid & 15, ty = tid >> 4;
    float acc[4][4];
    #pragma unroll
    for (int i = 0; i < 4; i++)
        #pragma unroll
        for (int j = 0; j < 4; j++) acc[i][j] = 0.f;

    #pragma unroll 8
    for (int d = 0; d < 64; d++) {
        float a0 = Qs[ty * 4 + 0][d], a1 = Qs[ty * 4 + 1][d];
        float a2 = Qs[ty * 4 + 2][d], a3 = Qs[ty * 4 + 3][d];
        float b0 = Cs[d][tx * 4 + 0], b1 = Cs[d][tx * 4 + 1];
        float b2 = Cs[d][tx * 4 + 2], b3 = Cs[d][tx * 4 + 3];
        acc[0][0] += a0 * b0; acc[0][1] += a0 * b1; acc[0][2] += a0 * b2; acc[0][3] += a0 * b3;
        acc[1][0] += a1 * b0; acc[1][1] += a1 * b1; acc[1][2] += a1 * b2; acc[1][3] += a1 * b3;
        acc[2][0] += a2 * b0; acc[2][1] += a2 * b1; acc[2][2] += a2 * b2; acc[2][3] += a2 * b3;
        acc[3][0] += a3 * b0; acc[3][1] += a3 * b1; acc[3][2] += a3 * b2; acc[3][3] += a3 * b3;
    }
    float* ob = outp + ((size_t)(b * NN_ + n0)) * DD + h * 64;
    #pragma unroll
    for (int i = 0; i < 4; i++) {
        float o[4];
        #pragma unroll
        for (int j = 0; j < 4; j++) o[j] = to_tf32(acc[i][j]);
        *(float4*)(ob + (size_t)(ty * 4 + i) * DD + tx * 4) = *(float4*)&o[0];
    }
}

// ---------------------------------------------------------------------------
// Launch sequence
// ---------------------------------------------------------------------------
extern "C" void kernel_launch(void* const* d_in, const int* in_sizes, int n_in,
                              void* d_out, int out_size) {
    (void)in_sizes; (void)n_in; (void)out_size;
    const float* x      = (const float*)d_in[0];
    const float* wt     = (const float*)d_in[1];
    const float* ln_q_g = (const float*)d_in[2];
    const float* ln_q_b = (const float*)d_in[3];
    const float* Wq     = (const float*)d_in[4];
    const float* bq     = (const float*)d_in[5];
    const float* ln_kv_g= (const float*)d_in[6];
    const float* ln_kv_b= (const float*)d_in[7];
    const float* Wkv    = (const float*)d_in[8];
    const float* bkv    = (const float*)d_in[9];
    const float* Wo     = (const float*)d_in[10];
    const float* bo     = (const float*)d_in[11];
    const float* ln_f_g = (const float*)d_in[12];
    const float* ln_f_b = (const float*)d_in[13];
    const float* W1     = (const float*)d_in[14];
    const float* b1     = (const float*)d_in[15];
    const float* W2     = (const float*)d_in[16];
    const float* b2     = (const float*)d_in[17];
    float* out = (float*)d_out;

    float *bufA, *buf1, *buf2, *buf3, *kv, *ctx;
    float *WqT, *WkvT, *WoT;
    int8_t *W1h, *W1l, *W2h, *W2l, *lnH, *lnL, *hH, *hL;
    cudaGetSymbolAddress((void**)&bufA, g_bufA);
    cudaGetSymbolAddress((void**)&buf1, g_buf1);
    cudaGetSymbolAddress((void**)&buf2, g_buf2);
    cudaGetSymbolAddress((void**)&buf3, g_buf3);
    cudaGetSymbolAddress((void**)&kv,   g_kv);
    cudaGetSymbolAddress((void**)&ctx,  g_ctx);
    cudaGetSymbolAddress((void**)&WqT,  g_WqT);
    cudaGetSymbolAddress((void**)&WkvT, g_WkvT);
    cudaGetSymbolAddress((void**)&WoT,  g_WoT);
    cudaGetSymbolAddress((void**)&W1h,  g_W1hT);
    cudaGetSymbolAddress((void**)&W1l,  g_W1lT);
    cudaGetSymbolAddress((void**)&W2h,  g_W2hT);
    cudaGetSymbolAddress((void**)&W2l,  g_W2lT);
    cudaGetSymbolAddress((void**)&lnH,  g_lnH);
    cudaGetSymbolAddress((void**)&lnL,  g_lnL);
    cudaGetSymbolAddress((void**)&hH,   g_hH);
    cudaGetSymbolAddress((void**)&hL,   g_hL);

    cudaFuncSetAttribute(tgemm<0>, cudaFuncAttributeMaxDynamicSharedMemorySize, DSMEM_BYTES);
    cudaFuncSetAttribute(tgemm<1>, cudaFuncAttributeMaxDynamicSharedMemorySize, DSMEM_BYTES);
    cudaFuncSetAttribute(i8gemm<0>, cudaFuncAttributeMaxDynamicSharedMemorySize, I8_DSMEM);
    cudaFuncSetAttribute(i8gemm<1>, cudaFuncAttributeMaxDynamicSharedMemorySize, I8_DSMEM);

    const float cA1 = (float)((double)S_LN * (double)S_WW * 16384.0);
    const float cB1 = (float)((double)S_LN * (double)S_WW * 128.0);
    const float cA2 = (float)((double)S_HH * (double)S_WW * 16384.0);
    const float cB2 = (float)((double)S_HH * (double)S_WW * 128.0);

    // 0. weight prep
    transpose_tf32<<<dim3(1024 / 32, 1024 / 32), dim3(32, 8)>>>(Wq,  WqT,  1024, 1024);
    transpose_tf32<<<dim3(2048 / 32, 1024 / 32), dim3(32, 8)>>>(Wkv, WkvT, 1024, 2048);
    transpose_tf32<<<dim3(1024 / 32, 1024 / 32), dim3(32, 8)>>>(Wo,  WoT,  1024, 1024);
    transpose_q8<<<dim3(4096 / 32, 1024 / 32), dim3(32, 8)>>>(W1, W1h, W1l, 1024, 4096);
    transpose_q8<<<dim3(1024 / 32, 4096 / 32), dim3(32, 8)>>>(W2, W2h, W2l, 4096, 1024);

    // 1. LN (attention path, tf32 out)
    ln_kernel_t<0><<<ROWS_X, 256>>>(x,  ln_q_g,  ln_q_b,  buf1, nullptr, nullptr);
    ln_kernel_t<0><<<ROWS_W, 256>>>(wt, ln_kv_g, ln_kv_b, bufA, nullptr, nullptr);

    // 2. q / kv projections (tf32)
    tgemm<0><<<dim3(DD / 128, ROWS_X / 256), 256, DSMEM_BYTES>>>(buf1, WqT, bq, nullptr,
                                                                 buf2, DD, DD);
    tgemm<0><<<dim3(2048 / 128, ROWS_W / 256), 256, DSMEM_BYTES>>>(bufA, WkvT, bkv, nullptr,
                                                                   kv, 2048, DD);

    // 3. softmaxes + linear attention core
    softmax_q_kernel<<<dim3(DD / 32, BB), dim3(32, 8)>>>(buf2);
    softmax_k_kernel<<<ROWS_W, 512>>>(kv);
    context_kernel<<<BB * HH, 256>>>(kv, ctx);
    apply_ctx_kernel<<<dim3(NN_ / 64, BB * HH), 256>>>(buf2, ctx, buf1);

    // 4. x2 = attn @ Wo + bo + x  (tf32)
    tgemm<1><<<dim3(DD / 128, ROWS_X / 256), 256, DSMEM_BYTES>>>(buf1, WoT, bo, x,
                                                                 buf3, DD, DD);

    // 5. LN(x2) -> int8 planes
    ln_kernel_t<1><<<ROWS_X, 256>>>(buf3, ln_f_g, ln_f_b, nullptr, lnH, lnL);

    // 6. h = silu(ln2 @ W1 + b1) -> int8 planes  (int8 dual-plane)
    i8gemm<0><<<dim3(4096 / 64, ROWS_X / 128), 128, I8_DSMEM>>>(
        lnH, lnL, W1h, W1l, b1, nullptr, nullptr, hH, hL, 4096, 1024,
        cA1, cB1, QMUL_H);

    // 7. out = h @ W2 + b2 + x2  (int8 dual-plane)
    i8gemm<1><<<dim3(DD / 64, ROWS_X / 128), 128, I8_DSMEM>>>(
        hH, hL, W2h, W2l, b2, buf3, out, nullptr, nullptr, DD, 4096,
        cA2, cB2, 0.f);
}

// round 9
// speedup vs baseline: 1.2700x; 1.2700x over previous
#include <cuda_runtime.h>
#include <math.h>
#include <stdint.h>

// ---------------------------------------------------------------------------
// Problem constants
// ---------------------------------------------------------------------------
#define BB 8
#define NN_ 4096
#define MM_ 1024
#define DD 1024
#define HH 16
#define SCALE_F 0.125f
#define EPS_F 1e-6f
#define ROWS_X (BB * NN_)   // 32768
#define ROWS_W (BB * MM_)   // 8192

// ---------------------------------------------------------------------------
// Scratch (static device globals)
// ---------------------------------------------------------------------------
__device__ float g_bufA[(size_t)ROWS_X * 4096];  // lnw (front), then FFN hidden
__device__ float g_buf1[(size_t)ROWS_X * DD];    // ln1 -> attn_out -> ln2
__device__ float g_buf2[(size_t)ROWS_X * DD];    // q (raw, pre-softmax)
__device__ float g_buf3[(size_t)ROWS_X * DD];    // x2
__device__ float g_kv[(size_t)ROWS_W * 2048];
__device__ float g_ctx[(size_t)BB * HH * 64 * 64];
__device__ float g_qM[(size_t)BB * DD];          // per-(b,channel) softmax max
__device__ float g_qS[(size_t)BB * DD];          // per-(b,channel) softmax inv-sum
// transposed (N,K) weights, tf32-rounded
__device__ float g_WqT[(size_t)1024 * 1024];
__device__ float g_WkvT[(size_t)2048 * 1024];
__device__ float g_WoT[(size_t)1024 * 1024];
__device__ float g_W1T[(size_t)4096 * 1024];
__device__ float g_W2T[(size_t)1024 * 4096];

// ---------------------------------------------------------------------------
// Helpers
// ---------------------------------------------------------------------------
__device__ __forceinline__ uint32_t smem_u32(const void* p) {
    uint32_t a;
    asm("{ .reg .u64 t; cvta.to.shared.u64 t, %1; cvt.u32.u64 %0, t; }"
        : "=r"(a) : "l"(p));
    return a;
}

__device__ __forceinline__ float to_tf32(float x) {
    uint32_t u;
    asm("cvt.rna.tf32.f32 %0, %1;" : "=r"(u) : "f"(x));
    return __uint_as_float(u);
}

__device__ __forceinline__ void cp_async16(uint32_t smem, const void* gmem) {
    asm volatile("cp.async.cg.shared.global [%0], [%1], 16;\n"
                 :: "r"(smem), "l"(gmem));
}
#define CP_COMMIT() asm volatile("cp.async.commit_group;" ::: "memory")

__device__ __forceinline__ uint32_t lds32(uint32_t addr) {
    uint32_t v;
    asm volatile("ld.shared.b32 %0, [%1];" : "=r"(v) : "r"(addr));
    return v;
}

// m16n8k8 tf32 MMA (sm_80+, arch-portable)
__device__ __forceinline__ void mma_tf32(float* d, const uint32_t* a,
                                         const uint32_t* b) {
    asm volatile(
        "mma.sync.aligned.m16n8k8.row.col.f32.tf32.tf32.f32 "
        "{%0,%1,%2,%3}, {%4,%5,%6,%7}, {%8,%9}, {%0,%1,%2,%3};"
        : "+f"(d[0]), "+f"(d[1]), "+f"(d[2]), "+f"(d[3])
        : "r"(a[0]), "r"(a[1]), "r"(a[2]), "r"(a[3]), "r"(b[0]), "r"(b[1]));
}

// smem fragment address: tile rows of 32 floats (128 B), XOR swizzle on 16B units
__device__ __forceinline__ uint32_t fragoff(int r, int c) {
    return (uint32_t)(r * 128 + (((c >> 2) ^ (r & 7)) << 4) + ((c & 3) << 2));
}

// ---------------------------------------------------------------------------
// tf32 mma.sync GEMM: C[M,N] = A[M,K] @ BT[N,K]^T + bias (+res | silu)
// CTA tile 256x128, 8 warps (4x2), warp tile 64x64, K-chunk=32,
// 4-stage cp.async pipeline with swizzled smem (48KB/stage).
// EP: 0 = +bias ; 1 = +bias +res ; 2 = tf32round(silu(+bias))
// ---------------------------------------------------------------------------
#define A_STAGE_BYTES 32768u       // 256 rows x 32 k x 4B
#define B_STAGE_BYTES 16384u       // 128 rows x 32 k x 4B
#define STAGE_BYTES (A_STAGE_BYTES + B_STAGE_BYTES)
#define NSTAGE 4
#define DSMEM_BYTES (NSTAGE * STAGE_BYTES)

template <int EP>
__global__ void __launch_bounds__(256)
tgemm(const float* __restrict__ A, const float* __restrict__ BT,
      const float* __restrict__ bias, const float* __restrict__ res,
      float* __restrict__ C, int Ncols, int K) {
    extern __shared__ char dsm[];
    const uint32_t smem0 = smem_u32(dsm);

    const int tid = threadIdx.x;
    const int lane = tid & 31, warp = tid >> 5;
    const int wy = warp >> 1, wx = warp & 1;        // 4x2 warp grid
    const int gid = lane >> 2, tig = lane & 3;      // mma fragment coords
    const int bm = blockIdx.y, bn = blockIdx.x;

    const float* Abase = A + (size_t)(bm * 256) * K;
    const float* Bbase = BT + (size_t)(bn * 128) * K;
    const int ntiles = K >> 5;

    float acc[4][8][4];
    #pragma unroll
    for (int mt = 0; mt < 4; mt++)
        #pragma unroll
        for (int nt = 0; nt < 8; nt++)
            #pragma unroll
            for (int r = 0; r < 4; r++) acc[mt][nt][r] = 0.f;

    // loader: A = 2048 16B units (256 thr x 8), B = 1024 (256 thr x 4)
    auto load_chunk = [&](int c) {
        const uint32_t so = smem0 + (uint32_t)(c % NSTAGE) * STAGE_BYTES;
        const int k0 = c << 5;
        #pragma unroll
        for (int t = 0; t < 8; t++) {
            const int i = tid + t * 256;
            const int r = i >> 3, u = i & 7;
            const uint32_t du = (uint32_t)((u ^ (r & 7)) << 4);
            cp_async16(so + (uint32_t)(r * 128) + du,
                       Abase + (size_t)r * K + k0 + u * 4);
        }
        #pragma unroll
        for (int t = 0; t < 4; t++) {
            const int i = tid + t * 256;
            const int r = i >> 3, u = i & 7;
            const uint32_t du = (uint32_t)((u ^ (r & 7)) << 4);
            cp_async16(so + A_STAGE_BYTES + (uint32_t)(r * 128) + du,
                       Bbase + (size_t)r * K + k0 + u * 4);
        }
        CP_COMMIT();
    };

    load_chunk(0);
    load_chunk(1);
    load_chunk(2);

    for (int c = 0; c < ntiles; c++) {
        asm volatile("cp.async.wait_group 2;" ::: "memory");
        __syncthreads();

        // keep exactly 3 groups in flight (empty commit keeps the count honest)
        if (c + 3 < ntiles) load_chunk(c + 3);
        else CP_COMMIT();

        const uint32_t sA = smem0 + (uint32_t)(c % NSTAGE) * STAGE_BYTES;
        const uint32_t sB = sA + A_STAGE_BYTES;

        #pragma unroll
        for (int ks = 0; ks < 4; ks++) {
            const int kc = ks * 8 + tig;
            uint32_t a[4][4];
            #pragma unroll
            for (int mt = 0; mt < 4; mt++) {
                const int r0 = wy * 64 + mt * 16 + gid;
                a[mt][0] = lds32(sA + fragoff(r0,     kc));
                a[mt][1] = lds32(sA + fragoff(r0 + 8, kc));
                a[mt][2] = lds32(sA + fragoff(r0,     kc + 4));
                a[mt][3] = lds32(sA + fragoff(r0 + 8, kc + 4));
            }
            #pragma unroll
            for (int nt = 0; nt < 8; nt++) {
                const int n0 = wx * 64 + nt * 8 + gid;
                uint32_t b[2];
                b[0] = lds32(sB + fragoff(n0, kc));
                b[1] = lds32(sB + fragoff(n0, kc + 4));
                #pragma unroll
                for (int mt = 0; mt < 4; mt++)
                    mma_tf32(acc[mt][nt], a[mt], b);
            }
        }
        __syncthreads();
    }

    // epilogue: thread owns rows {r0, r0+8}, col pairs per n-tile
    #pragma unroll
    for (int mt = 0; mt < 4; mt++) {
        const int r0 = bm * 256 + wy * 64 + mt * 16 + gid;
        #pragma unroll
        for (int nt = 0; nt < 8; nt++) {
            const int col = bn * 128 + wx * 64 + nt * 8 + tig * 2;
            float2 b2 = *(const float2*)(bias + col);
            float v0 = acc[mt][nt][0] + b2.x;
            float v1 = acc[mt][nt][1] + b2.y;
            float v2 = acc[mt][nt][2] + b2.x;
            float v3 = acc[mt][nt][3] + b2.y;
            if (EP == 1) {
                float2 ra = *(const float2*)(res + (size_t)r0 * Ncols + col);
                float2 rb = *(const float2*)(res + (size_t)(r0 + 8) * Ncols + col);
                v0 += ra.x; v1 += ra.y; v2 += rb.x; v3 += rb.y;
            }
            if (EP == 2) {
                v0 = to_tf32(v0 * (1.f / (1.f + __expf(-v0))));
                v1 = to_tf32(v1 * (1.f / (1.f + __expf(-v1))));
                v2 = to_tf32(v2 * (1.f / (1.f + __expf(-v2))));
                v3 = to_tf32(v3 * (1.f / (1.f + __expf(-v3))));
            }
            *(float2*)(C + (size_t)r0 * Ncols + col)       = make_float2(v0, v1);
            *(float2*)(C + (size_t)(r0 + 8) * Ncols + col) = make_float2(v2, v3);
        }
    }
}

// ---------------------------------------------------------------------------
// Weight transpose: in[K][N] -> out[N][K], tf32-rounded output
// ---------------------------------------------------------------------------
__global__ void transpose_tf32(const float* __restrict__ in, float* __restrict__ out,
                               int K, int N) {
    __shared__ float t[32][33];
    const int bx = blockIdx.x * 32;  // n
    const int by = blockIdx.y * 32;  // k
    const int x = threadIdx.x, y = threadIdx.y;
    #pragma unroll
    for (int i = 0; i < 32; i += 8)
        t[y + i][x] = in[(size_t)(by + y + i) * N + bx + x];
    __syncthreads();
    #pragma unroll
    for (int i = 0; i < 32; i += 8)
        out[(size_t)(bx + y + i) * K + by + x] = to_tf32(t[x][y + i]);
}

// ---------------------------------------------------------------------------
// LayerNorm (tf32-rounded output: it only feeds GEMMs)
// ---------------------------------------------------------------------------
__global__ void ln_kernel(const float* __restrict__ x, const float* __restrict__ g,
                          const float* __restrict__ bta, float* __restrict__ y) {
    const int tid = threadIdx.x;
    const size_t row = blockIdx.x;
    float4 v = ((const float4*)(x + row * DD))[tid];
    __shared__ float red[32];

    float s = v.x + v.y + v.z + v.w;
    #pragma unroll
    for (int o = 16; o; o >>= 1) s += __shfl_xor_sync(0xffffffffu, s, o);
    if ((tid & 31) == 0) red[tid >> 5] = s;
    __syncthreads();
    if (tid < 32) {
        float t = (tid < 8) ? red[tid] : 0.f;
        #pragma unroll
        for (int o = 4; o; o >>= 1) t += __shfl_xor_sync(0xffffffffu, t, o);
        if (tid == 0) red[0] = t;
    }
    __syncthreads();
    const float mean = red[0] * (1.f / DD);

    float dx = v.x - mean, dy = v.y - mean, dz = v.z - mean, dw = v.w - mean;
    float ss = dx * dx + dy * dy + dz * dz + dw * dw;
    #pragma unroll
    for (int o = 16; o; o >>= 1) ss += __shfl_xor_sync(0xffffffffu, ss, o);
    __syncthreads();
    if ((tid & 31) == 0) red[tid >> 5] = ss;
    __syncthreads();
    if (tid < 32) {
        float t = (tid < 8) ? red[tid] : 0.f;
        #pragma unroll
        for (int o = 4; o; o >>= 1) t += __shfl_xor_sync(0xffffffffu, t, o);
        if (tid == 0) red[0] = t;
    }
    __syncthreads();
    const float rstd = rsqrtf(red[0] * (1.f / DD) + EPS_F);

    float4 gg = ((const float4*)g)[tid];
    float4 bb = ((const float4*)bta)[tid];
    float4 o4;
    o4.x = to_tf32(dx * rstd * gg.x + bb.x);
    o4.y = to_tf32(dy * rstd * gg.y + bb.y);
    o4.z = to_tf32(dz * rstd * gg.z + bb.z);
    o4.w = to_tf32(dw * rstd * gg.w + bb.w);
    ((float4*)(y + row * DD))[tid] = o4;
}

// ---------------------------------------------------------------------------
// softmax stats over N axis of q[B,N,D] per (b, channel): writes M and 1/S
// ---------------------------------------------------------------------------
__global__ void softmax_q_stats(const float* __restrict__ q,
                                float* __restrict__ qM, float* __restrict__ qS) {
    const int b = blockIdx.y;
    const int c = (blockIdx.x << 5) + threadIdx.x;
    const int ty = threadIdx.y;
    const float* base = q + (size_t)b * NN_ * DD + c;

    float m = -1e30f, s = 0.f;
    for (int n = ty; n < NN_; n += 8) {
        float v = base[(size_t)n * DD];
        if (v > m) { s = s * __expf(m - v) + 1.f; m = v; }
        else       { s += __expf(v - m); }
    }
    __shared__ float sm[8][32], ssum[8][32];
    sm[ty][threadIdx.x] = m; ssum[ty][threadIdx.x] = s;
    __syncthreads();
    if (ty == 0) {
        float Mv = -1e30f;
        #pragma unroll
        for (int i = 0; i < 8; i++) Mv = fmaxf(Mv, sm[i][threadIdx.x]);
        float Sv = 0.f;
        #pragma unroll
        for (int i = 0; i < 8; i++)
            Sv += ssum[i][threadIdx.x] * __expf(sm[i][threadIdx.x] - Mv);
        qM[b * DD + c] = Mv;
        qS[b * DD + c] = 1.f / Sv;
    }
}

// softmax over each 64-wide head chunk of k
__global__ void softmax_k_kernel(float* __restrict__ kv) {
    const size_t row = blockIdx.x;
    const int w = threadIdx.x >> 5, lane = threadIdx.x & 31;
    float* p = kv + row * 2048 + w * 64;
    float a = p[lane], c = p[lane + 32];
    float m = fmaxf(a, c);
    #pragma unroll
    for (int o = 16; o; o >>= 1) m = fmaxf(m, __shfl_xor_sync(0xffffffffu, m, o));
    float ea = __expf(a - m), ec = __expf(c - m);
    float s = ea + ec;
    #pragma unroll
    for (int o = 16; o; o >>= 1) s += __shfl_xor_sync(0xffffffffu, s, o);
    const float inv = 1.f / s;
    p[lane] = ea * inv; p[lane + 32] = ec * inv;
}

// context[b,h,:,:] = SCALE * k^T v  (64x64 per head)
__global__ void context_kernel(const float* __restrict__ kv, float* __restrict__ ctx) {
    const int bh = blockIdx.x;
    const int b = bh >> 4, h = bh & 15;
    __shared__ float Ks[64][64];
    __shared__ float Vs[64][64];
    const int tid = threadIdx.x;
    const int tx = tid & 15, ty = tid >> 4;
    const float* kvb = kv + (size_t)b * MM_ * 2048 + h * 64;

    float acc[4][4];
    #pragma unroll
    for (int i = 0; i < 4; i++)
        #pragma unroll
        for (int j = 0; j < 4; j++) acc[i][j] = 0.f;

    for (int m0 = 0; m0 < MM_; m0 += 64) {
        for (int i = tid; i < 1024; i += 256) {
            int r = i >> 4, c4 = (i & 15) << 2;
            const float* rp = kvb + (size_t)(m0 + r) * 2048 + c4;
            *(float4*)&Ks[r][c4] = *(const float4*)rp;
            *(float4*)&Vs[r][c4] = *(const float4*)(rp + 1024);
        }
        __syncthreads();
        #pragma unroll 8
        for (int mm = 0; mm < 64; mm++) {
            float a0 = Ks[mm][ty * 4 + 0], a1 = Ks[mm][ty * 4 + 1];
            float a2 = Ks[mm][ty * 4 + 2], a3 = Ks[mm][ty * 4 + 3];
            float b0 = Vs[mm][tx * 4 + 0], b1 = Vs[mm][tx * 4 + 1];
            float b2 = Vs[mm][tx * 4 + 2], b3 = Vs[mm][tx * 4 + 3];
            acc[0][0] += a0 * b0; acc[0][1] += a0 * b1; acc[0][2] += a0 * b2; acc[0][3] += a0 * b3;
            acc[1][0] += a1 * b0; acc[1][1] += a1 * b1; acc[1][2] += a1 * b2; acc[1][3] += a1 * b3;
            acc[2][0] += a2 * b0; acc[2][1] += a2 * b1; acc[2][2] += a2 * b2; acc[2][3] += a2 * b3;
            acc[3][0] += a3 * b0; acc[3][1] += a3 * b1; acc[3][2] += a3 * b2; acc[3][3] += a3 * b3;
        }
        __syncthreads();
    }
    float* cb = ctx + (size_t)bh * 64 * 64;
    #pragma unroll
    for (int i = 0; i < 4; i++) {
        float o[4];
        #pragma unroll
        for (int j = 0; j < 4; j++) o[j] = acc[i][j] * SCALE_F;
        *(float4*)(cb + (ty * 4 + i) * 64 + tx * 4) = *(float4*)&o[0];
    }
}

// out[b,n,h*64+e] = sum_d softmax_q(q)[b,n,h*64+d] * ctx[b,h,d,e]
// softmax applied on the fly from (qM, qS); output tf32-rounded (feeds Wo GEMM)
__global__ void apply_ctx_kernel(const float* __restrict__ q,
                                 const float* __restrict__ qM,
                                 const float* __restrict__ qS,
                                 const float* __restrict__ ctx,
                                 float* __restrict__ outp) {
    const int bh = blockIdx.y;
    const int b = bh >> 4, h = bh & 15;
    const int n0 = blockIdx.x << 6;
    __shared__ float Cs[64][64];
    __shared__ float Qs[64][64];
    __shared__ float sM[64], sS[64];
    const int tid = threadIdx.x;
    const float* qb = q + ((size_t)(b * NN_ + n0)) * DD + h * 64;
    const float* cb = ctx + (size_t)bh * 64 * 64;

    if (tid < 64) {
        sM[tid] = qM[b * DD + h * 64 + tid];
        sS[tid] = qS[b * DD + h * 64 + tid];
    }
    __syncthreads();

    for (int i = tid; i < 1024; i += 256) {
        int r = i >> 4, c4 = (i & 15) << 2;
        *(float4*)&Cs[r][c4] = *(const float4*)(cb + r * 64 + c4);
        float4 qa = *(const float4*)(qb + (size_t)r * DD + c4);
        qa.x = __expf(qa.x - sM[c4 + 0]) * sS[c4 + 0];
        qa.y = __expf(qa.y - sM[c4 + 1]) * sS[c4 + 1];
        qa.z = __expf(qa.z - sM[c4 + 2]) * sS[c4 + 2];
        qa.w = __expf(qa.w - sM[c4 + 3]) * sS[c4 + 3];
        *(float4*)&Qs[r][c4] = qa;
    }
    __syncthreads();

    const int tx = tid & 15, ty = tid >> 4;
    float acc[4][4];
    #pragma unroll
    for (int i = 0; i < 4; i++)
        #pragma unroll
        for (int j = 0; j < 4; j++) acc[i][j] = 0.f;

    #pragma unroll 8
    for (int d = 0; d < 64; d++) {
        float a0 = Qs[ty * 4 + 0][d], a1 = Qs[ty * 4 + 1][d];
        float a2 = Qs[ty * 4 + 2][d], a3 = Qs[ty * 4 + 3][d];
        float b0 = Cs[d][tx * 4 + 0], b1 = Cs[d][tx * 4 + 1];
        float b2 = Cs[d][tx * 4 + 2], b3 = Cs[d][tx * 4 + 3];
        acc[0][0] += a0 * b0; acc[0][1] += a0 * b1; acc[0][2] += a0 * b2; acc[0][3] += a0 * b3;
        acc[1][0] += a1 * b0; acc[1][1] += a1 * b1; acc[1][2] += a1 * b2; acc[1][3] += a1 * b3;
        acc[2][0] += a2 * b0; acc[2][1] += a2 * b1; acc[2][2] += a2 * b2; acc[2][3] += a2 * b3;
        acc[3][0] += a3 * b0; acc[3][1] += a3 * b1; acc[3][2] += a3 * b2; acc[3][3] += a3 * b3;
    }
    float* ob = outp + ((size_t)(b * NN_ + n0)) * DD + h * 64;
    #pragma unroll
    for (int i = 0; i < 4; i++) {
        float o[4];
        #pragma unroll
        for (int j = 0; j < 4; j++) o[j] = to_tf32(acc[i][j]);
        *(float4*)(ob + (size_t)(ty * 4 + i) * DD + tx * 4) = *(float4*)&o[0];
    }
}

// ---------------------------------------------------------------------------
// Launch sequence
// ---------------------------------------------------------------------------
extern "C" void kernel_launch(void* const* d_in, const int* in_sizes, int n_in,
                              void* d_out, int out_size) {
    (void)in_sizes; (void)n_in; (void)out_size;
    const float* x      = (const float*)d_in[0];
    const float* wt     = (const float*)d_in[1];
    const float* ln_q_g = (const float*)d_in[2];
    const float* ln_q_b = (const float*)d_in[3];
    const float* Wq     = (const float*)d_in[4];
    const float* bq     = (const float*)d_in[5];
    const float* ln_kv_g= (const float*)d_in[6];
    const float* ln_kv_b= (const float*)d_in[7];
    const float* Wkv    = (const float*)d_in[8];
    const float* bkv    = (const float*)d_in[9];
    const float* Wo     = (const float*)d_in[10];
    const float* bo     = (const float*)d_in[11];
    const float* ln_f_g = (const float*)d_in[12];
    const float* ln_f_b = (const float*)d_in[13];
    const float* W1     = (const float*)d_in[14];
    const float* b1     = (const float*)d_in[15];
    const float* W2     = (const float*)d_in[16];
    const float* b2     = (const float*)d_in[17];
    float* out = (float*)d_out;

    float *bufA, *buf1, *buf2, *buf3, *kv, *ctx, *qM, *qS;
    float *WqT, *WkvT, *WoT, *W1T, *W2T;
    cudaGetSymbolAddress((void**)&bufA, g_bufA);
    cudaGetSymbolAddress((void**)&buf1, g_buf1);
    cudaGetSymbolAddress((void**)&buf2, g_buf2);
    cudaGetSymbolAddress((void**)&buf3, g_buf3);
    cudaGetSymbolAddress((void**)&kv,   g_kv);
    cudaGetSymbolAddress((void**)&ctx,  g_ctx);
    cudaGetSymbolAddress((void**)&qM,   g_qM);
    cudaGetSymbolAddress((void**)&qS,   g_qS);
    cudaGetSymbolAddress((void**)&WqT,  g_WqT);
    cudaGetSymbolAddress((void**)&WkvT, g_WkvT);
    cudaGetSymbolAddress((void**)&WoT,  g_WoT);
    cudaGetSymbolAddress((void**)&W1T,  g_W1T);
    cudaGetSymbolAddress((void**)&W2T,  g_W2T);

    cudaFuncSetAttribute(tgemm<0>, cudaFuncAttributeMaxDynamicSharedMemorySize, DSMEM_BYTES);
    cudaFuncSetAttribute(tgemm<1>, cudaFuncAttributeMaxDynamicSharedMemorySize, DSMEM_BYTES);
    cudaFuncSetAttribute(tgemm<2>, cudaFuncAttributeMaxDynamicSharedMemorySize, DSMEM_BYTES);

    // 0. transpose + tf32-round weights
    transpose_tf32<<<dim3(1024 / 32, 1024 / 32), dim3(32, 8)>>>(Wq,  WqT,  1024, 1024);
    transpose_tf32<<<dim3(2048 / 32, 1024 / 32), dim3(32, 8)>>>(Wkv, WkvT, 1024, 2048);
    transpose_tf32<<<dim3(1024 / 32, 1024 / 32), dim3(32, 8)>>>(Wo,  WoT,  1024, 1024);
    transpose_tf32<<<dim3(4096 / 32, 1024 / 32), dim3(32, 8)>>>(W1,  W1T,  1024, 4096);
    transpose_tf32<<<dim3(1024 / 32, 4096 / 32), dim3(32, 8)>>>(W2,  W2T,  4096, 1024);

    // 1. LN
    ln_kernel<<<ROWS_X, 256>>>(x,  ln_q_g,  ln_q_b,  buf1);
    ln_kernel<<<ROWS_W, 256>>>(wt, ln_kv_g, ln_kv_b, bufA);

    // 2. q / kv projections (tf32 mma.sync, 256x128 tiles)
    tgemm<0><<<dim3(DD / 128, ROWS_X / 256), 256, DSMEM_BYTES>>>(buf1, WqT, bq, nullptr,
                                                                 buf2, DD, DD);
    tgemm<0><<<dim3(2048 / 128, ROWS_W / 256), 256, DSMEM_BYTES>>>(bufA, WkvT, bkv, nullptr,
                                                                   kv, 2048, DD);

    // 3. softmax stats + linear attention core (q softmax fused into apply)
    softmax_q_stats<<<dim3(DD / 32, BB), dim3(32, 8)>>>(buf2, qM, qS);
    softmax_k_kernel<<<ROWS_W, 512>>>(kv);
    context_kernel<<<BB * HH, 256>>>(kv, ctx);
    apply_ctx_kernel<<<dim3(NN_ / 64, BB * HH), 256>>>(buf2, qM, qS, ctx, buf1);

    // 4. x2 = attn @ Wo + bo + x
    tgemm<1><<<dim3(DD / 128, ROWS_X / 256), 256, DSMEM_BYTES>>>(buf1, WoT, bo, x,
                                                                 buf3, DD, DD);

    // 5. LN(x2)
    ln_kernel<<<ROWS_X, 256>>>(buf3, ln_f_g, ln_f_b, buf1);

    // 6. h = silu(ln2 @ W1 + b1)
    tgemm<2><<<dim3(4096 / 128, ROWS_X / 256), 256, DSMEM_BYTES>>>(buf1, W1T, b1, nullptr,
                                                                   bufA, 4096, DD);

    // 7. out = h @ W2 + b2 + x2
    tgemm<1><<<dim3(DD / 128, ROWS_X / 256), 256, DSMEM_BYTES>>>(bufA, W2T, b2, buf3,
                                                                 out, DD, 4096);
}

// round 10
// speedup vs baseline: 2.1902x; 1.7245x over previous
#include <cuda_runtime.h>
#include <cuda_fp16.h>
#include <math.h>
#include <stdint.h>

// ---------------------------------------------------------------------------
// Problem constants
// ---------------------------------------------------------------------------
#define BB 8
#define NN_ 4096
#define MM_ 1024
#define DD 1024
#define HH 16
#define SCALE_F 0.125f
#define EPS_F 1e-6f
#define ROWS_X (BB * NN_)   // 32768
#define ROWS_W (BB * MM_)   // 8192

// ---------------------------------------------------------------------------
// Scratch (static device globals)
// ---------------------------------------------------------------------------
__device__ __half g_bufA[(size_t)ROWS_X * 4096]; // lnw (front), then FFN hidden h
__device__ __half g_buf1[(size_t)ROWS_X * DD];   // ln1 -> attn_out -> ln2 (half)
__device__ float  g_buf2[(size_t)ROWS_X * DD];   // q (raw fp32, pre-softmax)
__device__ float  g_buf3[(size_t)ROWS_X * DD];   // x2 (fp32)
__device__ float  g_kv[(size_t)ROWS_W * 2048];
__device__ float  g_ctx[(size_t)BB * HH * 64 * 64];
__device__ float  g_qM[(size_t)BB * DD];
__device__ float  g_qS[(size_t)BB * DD];
// transposed (N,K) weights, fp16
__device__ __half g_WqT[(size_t)1024 * 1024];
__device__ __half g_WkvT[(size_t)2048 * 1024];
__device__ __half g_WoT[(size_t)1024 * 1024];
__device__ __half g_W1T[(size_t)4096 * 1024];
__device__ __half g_W2T[(size_t)1024 * 4096];

// ---------------------------------------------------------------------------
// Helpers
// ---------------------------------------------------------------------------
__device__ __forceinline__ uint32_t smem_u32(const void* p) {
    uint32_t a;
    asm("{ .reg .u64 t; cvta.to.shared.u64 t, %1; cvt.u32.u64 %0, t; }"
        : "=r"(a) : "l"(p));
    return a;
}

__device__ __forceinline__ void cp_async16(uint32_t smem, const void* gmem) {
    asm volatile("cp.async.cg.shared.global [%0], [%1], 16;\n"
                 :: "r"(smem), "l"(gmem));
}
#define CP_COMMIT() asm volatile("cp.async.commit_group;" ::: "memory")

__device__ __forceinline__ uint32_t lds32(uint32_t addr) {
    uint32_t v;
    asm volatile("ld.shared.b32 %0, [%1];" : "=r"(v) : "r"(addr));
    return v;
}

// m16n8k16 fp16 MMA with fp32 accumulate (sm_80+, arch-portable)
__device__ __forceinline__ void mma_f16(float* d, const uint32_t* a,
                                        const uint32_t* b) {
    asm volatile(
        "mma.sync.aligned.m16n8k16.row.col.f32.f16.f16.f32 "
        "{%0,%1,%2,%3}, {%4,%5,%6,%7}, {%8,%9}, {%0,%1,%2,%3};"
        : "+f"(d[0]), "+f"(d[1]), "+f"(d[2]), "+f"(d[3])
        : "r"(a[0]), "r"(a[1]), "r"(a[2]), "r"(a[3]), "r"(b[0]), "r"(b[1]));
}

// smem fragment address: tile rows of 128B (64 fp16), XOR swizzle on 16B units
__device__ __forceinline__ uint32_t frag16(int r, int byteoff) {
    return (uint32_t)(r * 128 + ((((byteoff >> 4) ^ (r & 7))) << 4) + (byteoff & 15));
}

// ---------------------------------------------------------------------------
// fp16 mma.sync GEMM: C[M,N] = A[M,K] @ BT[N,K]^T + bias (+res | silu->half)
// CTA tile 256x128, 8 warps (4x2), warp tile 64x64, K-chunk=64 (4 x k16),
// 4-stage cp.async pipeline with swizzled smem (48KB/stage).
// EP: 0 = +bias -> fp32 ; 1 = +bias +res -> fp32 ; 2 = silu(+bias) -> half
// ---------------------------------------------------------------------------
#define A_STAGE_BYTES 32768u       // 256 rows x 64 k x 2B
#define B_STAGE_BYTES 16384u       // 128 rows x 64 k x 2B
#define STAGE_BYTES (A_STAGE_BYTES + B_STAGE_BYTES)
#define NSTAGE 4
#define DSMEM_BYTES (NSTAGE * STAGE_BYTES)

template <int EP>
__global__ void __launch_bounds__(256)
hgemm(const __half* __restrict__ A, const __half* __restrict__ BT,
      const float* __restrict__ bias, const float* __restrict__ res,
      float* __restrict__ C, __half* __restrict__ Ch, int Ncols, int K) {
    extern __shared__ char dsm[];
    const uint32_t smem0 = smem_u32(dsm);

    const int tid = threadIdx.x;
    const int lane = tid & 31, warp = tid >> 5;
    const int wy = warp >> 1, wx = warp & 1;        // 4x2 warp grid
    const int gid = lane >> 2, tig = lane & 3;      // mma fragment coords
    const int bm = blockIdx.y, bn = blockIdx.x;

    const __half* Abase = A + (size_t)(bm * 256) * K;
    const __half* Bbase = BT + (size_t)(bn * 128) * K;
    const int ntiles = K >> 6;                      // 64 k per chunk

    float acc[4][8][4];
    #pragma unroll
    for (int mt = 0; mt < 4; mt++)
        #pragma unroll
        for (int nt = 0; nt < 8; nt++)
            #pragma unroll
            for (int r = 0; r < 4; r++) acc[mt][nt][r] = 0.f;

    // loader: A = 2048 16B units (256 thr x 8), B = 1024 (256 thr x 4)
    auto load_chunk = [&](int c) {
        const uint32_t so = smem0 + (uint32_t)(c % NSTAGE) * STAGE_BYTES;
        const int k0 = c << 6;
        #pragma unroll
        for (int t = 0; t < 8; t++) {
            const int i = tid + t * 256;
            const int r = i >> 3, u = i & 7;
            const uint32_t du = (uint32_t)((u ^ (r & 7)) << 4);
            cp_async16(so + (uint32_t)(r * 128) + du,
                       Abase + (size_t)r * K + k0 + u * 8);
        }
        #pragma unroll
        for (int t = 0; t < 4; t++) {
            const int i = tid + t * 256;
            const int r = i >> 3, u = i & 7;
            const uint32_t du = (uint32_t)((u ^ (r & 7)) << 4);
            cp_async16(so + A_STAGE_BYTES + (uint32_t)(r * 128) + du,
                       Bbase + (size_t)r * K + k0 + u * 8);
        }
        CP_COMMIT();
    };

    load_chunk(0);
    load_chunk(1);
    load_chunk(2);

    for (int c = 0; c < ntiles; c++) {
        asm volatile("cp.async.wait_group 2;" ::: "memory");
        __syncthreads();

        if (c + 3 < ntiles) load_chunk(c + 3);
        else CP_COMMIT();

        const uint32_t sA = smem0 + (uint32_t)(c % NSTAGE) * STAGE_BYTES;
        const uint32_t sB = sA + A_STAGE_BYTES;

        #pragma unroll
        for (int ks = 0; ks < 4; ks++) {
            const int kb = ks * 32 + 4 * tig;       // byte offset of k-pair
            uint32_t a[4][4];
            #pragma unroll
            for (int mt = 0; mt < 4; mt++) {
                const int r0 = wy * 64 + mt * 16 + gid;
                a[mt][0] = lds32(sA + frag16(r0,     kb));
                a[mt][1] = lds32(sA + frag16(r0 + 8, kb));
                a[mt][2] = lds32(sA + frag16(r0,     kb + 16));
                a[mt][3] = lds32(sA + frag16(r0 + 8, kb + 16));
            }
            #pragma unroll
            for (int nt = 0; nt < 8; nt++) {
                const int n0 = wx * 64 + nt * 8 + gid;
                uint32_t b[2];
                b[0] = lds32(sB + frag16(n0, kb));
                b[1] = lds32(sB + frag16(n0, kb + 16));
                #pragma unroll
                for (int mt = 0; mt < 4; mt++)
                    mma_f16(acc[mt][nt], a[mt], b);
            }
        }
        __syncthreads();
    }

    // epilogue
    #pragma unroll
    for (int mt = 0; mt < 4; mt++) {
        const int r0 = bm * 256 + wy * 64 + mt * 16 + gid;
        #pragma unroll
        for (int nt = 0; nt < 8; nt++) {
            const int col = bn * 128 + wx * 64 + nt * 8 + tig * 2;
            float2 b2 = *(const float2*)(bias + col);
            float v0 = acc[mt][nt][0] + b2.x;
            float v1 = acc[mt][nt][1] + b2.y;
            float v2 = acc[mt][nt][2] + b2.x;
            float v3 = acc[mt][nt][3] + b2.y;
            if (EP == 1) {
                float2 ra = *(const float2*)(res + (size_t)r0 * Ncols + col);
                float2 rb = *(const float2*)(res + (size_t)(r0 + 8) * Ncols + col);
                v0 += ra.x; v1 += ra.y; v2 += rb.x; v3 += rb.y;
            }
            if (EP == 2) {
                v0 = v0 * (1.f / (1.f + __expf(-v0)));
                v1 = v1 * (1.f / (1.f + __expf(-v1)));
                v2 = v2 * (1.f / (1.f + __expf(-v2)));
                v3 = v3 * (1.f / (1.f + __expf(-v3)));
                *(__half2*)(Ch + (size_t)r0 * Ncols + col) =
                    __floats2half2_rn(v0, v1);
                *(__half2*)(Ch + (size_t)(r0 + 8) * Ncols + col) =
                    __floats2half2_rn(v2, v3);
            } else {
                *(float2*)(C + (size_t)r0 * Ncols + col)       = make_float2(v0, v1);
                *(float2*)(C + (size_t)(r0 + 8) * Ncols + col) = make_float2(v2, v3);
            }
        }
    }
}

// ---------------------------------------------------------------------------
// Weight transpose: in[K][N] fp32 -> out[N][K] fp16
// ---------------------------------------------------------------------------
__global__ void transpose_h(const float* __restrict__ in, __half* __restrict__ out,
                            int K, int N) {
    __shared__ float t[32][33];
    const int bx = blockIdx.x * 32;  // n
    const int by = blockIdx.y * 32;  // k
    const int x = threadIdx.x, y = threadIdx.y;
    #pragma unroll
    for (int i = 0; i < 32; i += 8)
        t[y + i][x] = in[(size_t)(by + y + i) * N + bx + x];
    __syncthreads();
    #pragma unroll
    for (int i = 0; i < 32; i += 8)
        out[(size_t)(bx + y + i) * K + by + x] = __float2half_rn(t[x][y + i]);
}

// ---------------------------------------------------------------------------
// LayerNorm: fp32 in -> fp16 out (feeds GEMMs only)
// ---------------------------------------------------------------------------
__global__ void ln_kernel(const float* __restrict__ x, const float* __restrict__ g,
                          const float* __restrict__ bta, __half* __restrict__ y) {
    const int tid = threadIdx.x;
    const size_t row = blockIdx.x;
    float4 v = ((const float4*)(x + row * DD))[tid];
    __shared__ float red[32];

    float s = v.x + v.y + v.z + v.w;
    #pragma unroll
    for (int o = 16; o; o >>= 1) s += __shfl_xor_sync(0xffffffffu, s, o);
    if ((tid & 31) == 0) red[tid >> 5] = s;
    __syncthreads();
    if (tid < 32) {
        float t = (tid < 8) ? red[tid] : 0.f;
        #pragma unroll
        for (int o = 4; o; o >>= 1) t += __shfl_xor_sync(0xffffffffu, t, o);
        if (tid == 0) red[0] = t;
    }
    __syncthreads();
    const float mean = red[0] * (1.f / DD);

    float dx = v.x - mean, dy = v.y - mean, dz = v.z - mean, dw = v.w - mean;
    float ss = dx * dx + dy * dy + dz * dz + dw * dw;
    #pragma unroll
    for (int o = 16; o; o >>= 1) ss += __shfl_xor_sync(0xffffffffu, ss, o);
    __syncthreads();
    if ((tid & 31) == 0) red[tid >> 5] = ss;
    __syncthreads();
    if (tid < 32) {
        float t = (tid < 8) ? red[tid] : 0.f;
        #pragma unroll
        for (int o = 4; o; o >>= 1) t += __shfl_xor_sync(0xffffffffu, t, o);
        if (tid == 0) red[0] = t;
    }
    __syncthreads();
    const float rstd = rsqrtf(red[0] * (1.f / DD) + EPS_F);

    float4 gg = ((const float4*)g)[tid];
    float4 bb = ((const float4*)bta)[tid];
    __half2* yp = (__half2*)(y + row * DD);
    yp[2 * tid]     = __floats2half2_rn(dx * rstd * gg.x + bb.x,
                                        dy * rstd * gg.y + bb.y);
    yp[2 * tid + 1] = __floats2half2_rn(dz * rstd * gg.z + bb.z,
                                        dw * rstd * gg.w + bb.w);
}

// ---------------------------------------------------------------------------
// softmax stats over N axis of q[B,N,D] per (b, channel): writes M and 1/S
// ---------------------------------------------------------------------------
__global__ void softmax_q_stats(const float* __restrict__ q,
                                float* __restrict__ qM, float* __restrict__ qS) {
    const int b = blockIdx.y;
    const int c = (blockIdx.x << 5) + threadIdx.x;
    const int ty = threadIdx.y;
    const float* base = q + (size_t)b * NN_ * DD + c;

    float m = -1e30f, s = 0.f;
    for (int n = ty; n < NN_; n += 8) {
        float v = base[(size_t)n * DD];
        if (v > m) { s = s * __expf(m - v) + 1.f; m = v; }
        else       { s += __expf(v - m); }
    }
    __shared__ float sm[8][32], ssum[8][32];
    sm[ty][threadIdx.x] = m; ssum[ty][threadIdx.x] = s;
    __syncthreads();
    if (ty == 0) {
        float Mv = -1e30f;
        #pragma unroll
        for (int i = 0; i < 8; i++) Mv = fmaxf(Mv, sm[i][threadIdx.x]);
        float Sv = 0.f;
        #pragma unroll
        for (int i = 0; i < 8; i++)
            Sv += ssum[i][threadIdx.x] * __expf(sm[i][threadIdx.x] - Mv);
        qM[b * DD + c] = Mv;
        qS[b * DD + c] = 1.f / Sv;
    }
}

// softmax over each 64-wide head chunk of k
__global__ void softmax_k_kernel(float* __restrict__ kv) {
    const size_t row = blockIdx.x;
    const int w = threadIdx.x >> 5, lane = threadIdx.x & 31;
    float* p = kv + row * 2048 + w * 64;
    float a = p[lane], c = p[lane + 32];
    float m = fmaxf(a, c);
    #pragma unroll
    for (int o = 16; o; o >>= 1) m = fmaxf(m, __shfl_xor_sync(0xffffffffu, m, o));
    float ea = __expf(a - m), ec = __expf(c - m);
    float s = ea + ec;
    #pragma unroll
    for (int o = 16; o; o >>= 1) s += __shfl_xor_sync(0xffffffffu, s, o);
    const float inv = 1.f / s;
    p[lane] = ea * inv; p[lane + 32] = ec * inv;
}

// context[b,h,:,:] = SCALE * k^T v  (64x64 per head)
__global__ void context_kernel(const float* __restrict__ kv, float* __restrict__ ctx) {
    const int bh = blockIdx.x;
    const int b = bh >> 4, h = bh & 15;
    __shared__ float Ks[64][64];
    __shared__ float Vs[64][64];
    const int tid = threadIdx.x;
    const int tx = tid & 15, ty = tid >> 4;
    const float* kvb = kv + (size_t)b * MM_ * 2048 + h * 64;

    float acc[4][4];
    #pragma unroll
    for (int i = 0; i < 4; i++)
        #pragma unroll
        for (int j = 0; j < 4; j++) acc[i][j] = 0.f;

    for (int m0 = 0; m0 < MM_; m0 += 64) {
        for (int i = tid; i < 1024; i += 256) {
            int r = i >> 4, c4 = (i & 15) << 2;
            const float* rp = kvb + (size_t)(m0 + r) * 2048 + c4;
            *(float4*)&Ks[r][c4] = *(const float4*)rp;
            *(float4*)&Vs[r][c4] = *(const float4*)(rp + 1024);
        }
        __syncthreads();
        #pragma unroll 8
        for (int mm = 0; mm < 64; mm++) {
            float a0 = Ks[mm][ty * 4 + 0], a1 = Ks[mm][ty * 4 + 1];
            float a2 = Ks[mm][ty * 4 + 2], a3 = Ks[mm][ty * 4 + 3];
            float b0 = Vs[mm][tx * 4 + 0], b1 = Vs[mm][tx * 4 + 1];
            float b2 = Vs[mm][tx * 4 + 2], b3 = Vs[mm][tx * 4 + 3];
            acc[0][0] += a0 * b0; acc[0][1] += a0 * b1; acc[0][2] += a0 * b2; acc[0][3] += a0 * b3;
            acc[1][0] += a1 * b0; acc[1][1] += a1 * b1; acc[1][2] += a1 * b2; acc[1][3] += a1 * b3;
            acc[2][0] += a2 * b0; acc[2][1] += a2 * b1; acc[2][2] += a2 * b2; acc[2][3] += a2 * b3;
            acc[3][0] += a3 * b0; acc[3][1] += a3 * b1; acc[3][2] += a3 * b2; acc[3][3] += a3 * b3;
        }
        __syncthreads();
    }
    float* cb = ctx + (size_t)bh * 64 * 64;
    #pragma unroll
    for (int i = 0; i < 4; i++) {
        float o[4];
        #pragma unroll
        for (int j = 0; j < 4; j++) o[j] = acc[i][j] * SCALE_F;
        *(float4*)(cb + (ty * 4 + i) * 64 + tx * 4) = *(float4*)&o[0];
    }
}

// out[b,n,h*64+e] = sum_d softmax_q(q)[b,n,h*64+d] * ctx[b,h,d,e]
// softmax applied on the fly; output fp16 (feeds Wo GEMM)
__global__ void apply_ctx_kernel(const float* __restrict__ q,
                                 const float* __restrict__ qM,
                                 const float* __restrict__ qS,
                                 const float* __restrict__ ctx,
                                 __half* __restrict__ outp) {
    const int bh = blockIdx.y;
    const int b = bh >> 4, h = bh & 15;
    const int n0 = blockIdx.x << 6;
    __shared__ float Cs[64][64];
    __shared__ float Qs[64][64];
    __shared__ float sM[64], sS[64];
    const int tid = threadIdx.x;
    const float* qb = q + ((size_t)(b * NN_ + n0)) * DD + h * 64;
    const float* cb = ctx + (size_t)bh * 64 * 64;

    if (tid < 64) {
        sM[tid] = qM[b * DD + h * 64 + tid];
        sS[tid] = qS[b * DD + h * 64 + tid];
    }
    __syncthreads();

    for (int i = tid; i < 1024; i += 256) {
        int r = i >> 4, c4 = (i & 15) << 2;
        *(float4*)&Cs[r][c4] = *(const float4*)(cb + r * 64 + c4);
        float4 qa = *(const float4*)(qb + (size_t)r * DD + c4);
        qa.x = __expf(qa.x - sM[c4 + 0]) * sS[c4 + 0];
        qa.y = __expf(qa.y - sM[c4 + 1]) * sS[c4 + 1];
        qa.z = __expf(qa.z - sM[c4 + 2]) * sS[c4 + 2];
        qa.w = __expf(qa.w - sM[c4 + 3]) * sS[c4 + 3];
        *(float4*)&Qs[r][c4] = qa;
    }
    __syncthreads();

    const int tx = tid & 15, ty = tid >> 4;
    float acc[4][4];
    #pragma unroll
    for (int i = 0; i < 4; i++)
        #pragma unroll
        for (int j = 0; j < 4; j++) acc[i][j] = 0.f;

    #pragma unroll 8
    for (int d = 0; d < 64; d++) {
        float a0 = Qs[ty * 4 + 0][d], a1 = Qs[ty * 4 + 1][d];
        float a2 = Qs[ty * 4 + 2][d], a3 = Qs[ty * 4 + 3][d];
        float b0 = Cs[d][tx * 4 + 0], b1 = Cs[d][tx * 4 + 1];
        float b2 = Cs[d][tx * 4 + 2], b3 = Cs[d][tx * 4 + 3];
        acc[0][0] += a0 * b0; acc[0][1] += a0 * b1; acc[0][2] += a0 * b2; acc[0][3] += a0 * b3;
        acc[1][0] += a1 * b0; acc[1][1] += a1 * b1; acc[1][2] += a1 * b2; acc[1][3] += a1 * b3;
        acc[2][0] += a2 * b0; acc[2][1] += a2 * b1; acc[2][2] += a2 * b2; acc[2][3] += a2 * b3;
        acc[3][0] += a3 * b0; acc[3][1] += a3 * b1; acc[3][2] += a3 * b2; acc[3][3] += a3 * b3;
    }
    __half* ob = outp + ((size_t)(b * NN_ + n0)) * DD + h * 64;
    #pragma unroll
    for (int i = 0; i < 4; i++) {
        __half2 h01 = __floats2half2_rn(acc[i][0], acc[i][1]);
        __half2 h23 = __floats2half2_rn(acc[i][2], acc[i][3]);
        __half2* op = (__half2*)(ob + (size_t)(ty * 4 + i) * DD + tx * 4);
        op[0] = h01;
        op[1] = h23;
    }
}

// ---------------------------------------------------------------------------
// Launch sequence
// ---------------------------------------------------------------------------
extern "C" void kernel_launch(void* const* d_in, const int* in_sizes, int n_in,
                              void* d_out, int out_size) {
    (void)in_sizes; (void)n_in; (void)out_size;
    const float* x      = (const float*)d_in[0];
    const float* wt     = (const float*)d_in[1];
    const float* ln_q_g = (const float*)d_in[2];
    const float* ln_q_b = (const float*)d_in[3];
    const float* Wq     = (const float*)d_in[4];
    const float* bq     = (const float*)d_in[5];
    const float* ln_kv_g= (const float*)d_in[6];
    const float* ln_kv_b= (const float*)d_in[7];
    const float* Wkv    = (const float*)d_in[8];
    const float* bkv    = (const float*)d_in[9];
    const float* Wo     = (const float*)d_in[10];
    const float* bo     = (const float*)d_in[11];
    const float* ln_f_g = (const float*)d_in[12];
    const float* ln_f_b = (const float*)d_in[13];
    const float* W1     = (const float*)d_in[14];
    const float* b1     = (const float*)d_in[15];
    const float* W2     = (const float*)d_in[16];
    const float* b2     = (const float*)d_in[17];
    float* out = (float*)d_out;

    __half *bufA, *buf1, *WqT, *WkvT, *WoT, *W1T, *W2T;
    float *buf2, *buf3, *kv, *ctx, *qM, *qS;
    cudaGetSymbolAddress((void**)&bufA, g_bufA);
    cudaGetSymbolAddress((void**)&buf1, g_buf1);
    cudaGetSymbolAddress((void**)&buf2, g_buf2);
    cudaGetSymbolAddress((void**)&buf3, g_buf3);
    cudaGetSymbolAddress((void**)&kv,   g_kv);
    cudaGetSymbolAddress((void**)&ctx,  g_ctx);
    cudaGetSymbolAddress((void**)&qM,   g_qM);
    cudaGetSymbolAddress((void**)&qS,   g_qS);
    cudaGetSymbolAddress((void**)&WqT,  g_WqT);
    cudaGetSymbolAddress((void**)&WkvT, g_WkvT);
    cudaGetSymbolAddress((void**)&WoT,  g_WoT);
    cudaGetSymbolAddress((void**)&W1T,  g_W1T);
    cudaGetSymbolAddress((void**)&W2T,  g_W2T);

    cudaFuncSetAttribute(hgemm<0>, cudaFuncAttributeMaxDynamicSharedMemorySize, DSMEM_BYTES);
    cudaFuncSetAttribute(hgemm<1>, cudaFuncAttributeMaxDynamicSharedMemorySize, DSMEM_BYTES);
    cudaFuncSetAttribute(hgemm<2>, cudaFuncAttributeMaxDynamicSharedMemorySize, DSMEM_BYTES);

    // 0. transpose weights -> fp16 [N][K]
    transpose_h<<<dim3(1024 / 32, 1024 / 32), dim3(32, 8)>>>(Wq,  WqT,  1024, 1024);
    transpose_h<<<dim3(2048 / 32, 1024 / 32), dim3(32, 8)>>>(Wkv, WkvT, 1024, 2048);
    transpose_h<<<dim3(1024 / 32, 1024 / 32), dim3(32, 8)>>>(Wo,  WoT,  1024, 1024);
    transpose_h<<<dim3(4096 / 32, 1024 / 32), dim3(32, 8)>>>(W1,  W1T,  1024, 4096);
    transpose_h<<<dim3(1024 / 32, 4096 / 32), dim3(32, 8)>>>(W2,  W2T,  4096, 1024);

    // 1. LN -> fp16
    ln_kernel<<<ROWS_X, 256>>>(x,  ln_q_g,  ln_q_b,  buf1);
    ln_kernel<<<ROWS_W, 256>>>(wt, ln_kv_g, ln_kv_b, bufA);

    // 2. q / kv projections (fp16 mma.sync)
    hgemm<0><<<dim3(DD / 128, ROWS_X / 256), 256, DSMEM_BYTES>>>(
        buf1, WqT, bq, nullptr, buf2, nullptr, DD, DD);
    hgemm<0><<<dim3(2048 / 128, ROWS_W / 256), 256, DSMEM_BYTES>>>(
        bufA, WkvT, bkv, nullptr, kv, nullptr, 2048, DD);

    // 3. softmax stats + linear attention core (q softmax fused into apply)
    softmax_q_stats<<<dim3(DD / 32, BB), dim3(32, 8)>>>(buf2, qM, qS);
    softmax_k_kernel<<<ROWS_W, 512>>>(kv);
    context_kernel<<<BB * HH, 256>>>(kv, ctx);
    apply_ctx_kernel<<<dim3(NN_ / 64, BB * HH), 256>>>(buf2, qM, qS, ctx, buf1);

    // 4. x2 = attn @ Wo + bo + x
    hgemm<1><<<dim3(DD / 128, ROWS_X / 256), 256, DSMEM_BYTES>>>(
        buf1, WoT, bo, x, buf3, nullptr, DD, DD);

    // 5. LN(x2) -> fp16
    ln_kernel<<<ROWS_X, 256>>>(buf3, ln_f_g, ln_f_b, buf1);

    // 6. h = silu(ln2 @ W1 + b1) -> fp16
    hgemm<2><<<dim3(4096 / 128, ROWS_X / 256), 256, DSMEM_BYTES>>>(
        buf1, W1T, b1, nullptr, nullptr, bufA, 4096, DD);

    // 7. out = h @ W2 + b2 + x2
    hgemm<1><<<dim3(DD / 128, ROWS_X / 256), 256, DSMEM_BYTES>>>(
        bufA, W2T, b2, buf3, out, nullptr, DD, 4096);
}

// round 11
// speedup vs baseline: 2.3737x; 1.0838x over previous
#include <cuda_runtime.h>
#include <cuda_fp16.h>
#include <math.h>
#include <stdint.h>

// ---------------------------------------------------------------------------
// Problem constants
// ---------------------------------------------------------------------------
#define BB 8
#define NN_ 4096
#define MM_ 1024
#define DD 1024
#define HH 16
#define SCALE_F 0.125f
#define EPS_F 1e-6f
#define ROWS_X (BB * NN_)   // 32768
#define ROWS_W (BB * MM_)   // 8192

// ---------------------------------------------------------------------------
// Scratch (static device globals)
// ---------------------------------------------------------------------------
__device__ __half g_bufA[(size_t)ROWS_X * 4096]; // lnw (front), then FFN hidden h
__device__ __half g_buf1[(size_t)ROWS_X * DD];   // ln1 -> attn_out -> ln2 (half)
__device__ float  g_buf2[(size_t)ROWS_X * DD];   // q (raw fp32, pre-softmax)
__device__ float  g_buf3[(size_t)ROWS_X * DD];   // x2 (fp32)
__device__ float  g_kv[(size_t)ROWS_W * 2048];
__device__ float  g_ctx[(size_t)BB * HH * 64 * 64];
__device__ float  g_qM[(size_t)BB * DD];
__device__ float  g_qS[(size_t)BB * DD];
// transposed (N,K) weights, fp16
__device__ __half g_WqT[(size_t)1024 * 1024];
__device__ __half g_WkvT[(size_t)2048 * 1024];
__device__ __half g_WoT[(size_t)1024 * 1024];
__device__ __half g_W1T[(size_t)4096 * 1024];
__device__ __half g_W2T[(size_t)1024 * 4096];

// ---------------------------------------------------------------------------
// Helpers
// ---------------------------------------------------------------------------
__device__ __forceinline__ uint32_t smem_u32(const void* p) {
    uint32_t a;
    asm("{ .reg .u64 t; cvta.to.shared.u64 t, %1; cvt.u32.u64 %0, t; }"
        : "=r"(a) : "l"(p));
    return a;
}

__device__ __forceinline__ void cp_async16(uint32_t smem, const void* gmem) {
    asm volatile("cp.async.cg.shared.global [%0], [%1], 16;\n"
                 :: "r"(smem), "l"(gmem));
}
#define CP_COMMIT() asm volatile("cp.async.commit_group;" ::: "memory")

// ldmatrix x4: four 8x8 b16 tiles, per-lane addresses
__device__ __forceinline__ void ldsm_x4(uint32_t* r, uint32_t addr) {
    asm volatile("ldmatrix.sync.aligned.m8n8.x4.shared.b16 {%0,%1,%2,%3}, [%4];"
                 : "=r"(r[0]), "=r"(r[1]), "=r"(r[2]), "=r"(r[3]) : "r"(addr));
}

// m16n8k16 fp16 MMA with fp32 accumulate (sm_80+, arch-portable)
__device__ __forceinline__ void mma_f16(float* d, const uint32_t* a,
                                        const uint32_t* b0, const uint32_t* b1) {
    asm volatile(
        "mma.sync.aligned.m16n8k16.row.col.f32.f16.f16.f32 "
        "{%0,%1,%2,%3}, {%4,%5,%6,%7}, {%8,%9}, {%0,%1,%2,%3};"
        : "+f"(d[0]), "+f"(d[1]), "+f"(d[2]), "+f"(d[3])
        : "r"(a[0]), "r"(a[1]), "r"(a[2]), "r"(a[3]), "r"(*b0), "r"(*b1));
}

// ---------------------------------------------------------------------------
// fp16 mma.sync GEMM: C[M,N] = A[M,K] @ BT[N,K]^T + bias (+res | silu->half)
// CTA tile 256x128, 8 warps (4x2), warp tile 64x64, K-chunk=64 (4 x k16),
// 4-stage cp.async pipeline, ldmatrix operand loads, fragment double-buffer.
// EP: 0 = +bias -> fp32 ; 1 = +bias +res -> fp32 ; 2 = silu(+bias) -> half
// ---------------------------------------------------------------------------
#define A_STAGE_BYTES 32768u       // 256 rows x 64 k x 2B
#define B_STAGE_BYTES 16384u       // 128 rows x 64 k x 2B
#define STAGE_BYTES (A_STAGE_BYTES + B_STAGE_BYTES)
#define NSTAGE 4
#define DSMEM_BYTES (NSTAGE * STAGE_BYTES)

template <int EP>
__global__ void __launch_bounds__(256)
hgemm(const __half* __restrict__ A, const __half* __restrict__ BT,
      const float* __restrict__ bias, const float* __restrict__ res,
      float* __restrict__ C, __half* __restrict__ Ch, int Ncols, int K) {
    extern __shared__ char dsm[];
    const uint32_t smem0 = smem_u32(dsm);

    const int tid = threadIdx.x;
    const int lane = tid & 31, warp = tid >> 5;
    const int wy = warp >> 1, wx = warp & 1;        // 4x2 warp grid
    const int gid = lane >> 2, tig = lane & 3;      // mma fragment coords
    const int bm = blockIdx.y, bn = blockIdx.x;

    const __half* Abase = A + (size_t)(bm * 256) * K;
    const __half* Bbase = BT + (size_t)(bn * 128) * K;
    const int ntiles = K >> 6;                      // 64 k per chunk

    // per-lane ldmatrix row/unit decomposition
    const int laneA_r = wy * 64 + ((lane >> 3) & 1) * 8 + (lane & 7);
    const int laneA_u = lane >> 4;                  // 16B unit select within pair
    const int laneA_s7 = laneA_r & 7;
    const int laneB_r = wx * 64 + (lane >> 4) * 8 + (lane & 7);
    const int laneB_u = (lane >> 3) & 1;
    const int laneB_s7 = laneB_r & 7;

    float acc[4][8][4];
    #pragma unroll
    for (int mt = 0; mt < 4; mt++)
        #pragma unroll
        for (int nt = 0; nt < 8; nt++)
            #pragma unroll
            for (int r = 0; r < 4; r++) acc[mt][nt][r] = 0.f;

    // loader: A = 2048 16B units (256 thr x 8), B = 1024 (256 thr x 4)
    auto load_chunk = [&](int c) {
        const uint32_t so = smem0 + (uint32_t)(c % NSTAGE) * STAGE_BYTES;
        const int k0 = c << 6;
        #pragma unroll
        for (int t = 0; t < 8; t++) {
            const int i = tid + t * 256;
            const int r = i >> 3, u = i & 7;
            const uint32_t du = (uint32_t)((u ^ (r & 7)) << 4);
            cp_async16(so + (uint32_t)(r * 128) + du,
                       Abase + (size_t)r * K + k0 + u * 8);
        }
        #pragma unroll
        for (int t = 0; t < 4; t++) {
            const int i = tid + t * 256;
            const int r = i >> 3, u = i & 7;
            const uint32_t du = (uint32_t)((u ^ (r & 7)) << 4);
            cp_async16(so + A_STAGE_BYTES + (uint32_t)(r * 128) + du,
                       Bbase + (size_t)r * K + k0 + u * 8);
        }
        CP_COMMIT();
    };

    load_chunk(0);
    load_chunk(1);
    load_chunk(2);

    uint32_t aF[2][4][4];     // [buf][mt][frag]
    uint32_t bF[2][4][4];     // [buf][nt-pair][frag]

    auto load_frags = [&](uint32_t sA, uint32_t sB, int ks, int buf) {
        const uint32_t uA = (uint32_t)(((ks * 2 + laneA_u) ^ laneA_s7) << 4);
        #pragma unroll
        for (int mt = 0; mt < 4; mt++)
            ldsm_x4(aF[buf][mt],
                    sA + (uint32_t)((laneA_r + mt * 16) * 128) + uA);
        const uint32_t uB = (uint32_t)(((ks * 2 + laneB_u) ^ laneB_s7) << 4);
        #pragma unroll
        for (int p = 0; p < 4; p++)
            ldsm_x4(bF[buf][p],
                    sB + (uint32_t)((laneB_r + p * 16) * 128) + uB);
    };

    for (int c = 0; c < ntiles; c++) {
        asm volatile("cp.async.wait_group 2;" ::: "memory");
        __syncthreads();

        const uint32_t sA = smem0 + (uint32_t)(c % NSTAGE) * STAGE_BYTES;
        const uint32_t sB = sA + A_STAGE_BYTES;

        load_frags(sA, sB, 0, 0);

        if (c + 3 < ntiles) load_chunk(c + 3);
        else CP_COMMIT();

        #pragma unroll
        for (int ks = 0; ks < 4; ks++) {
            const int cb = ks & 1;
            if (ks < 3) load_frags(sA, sB, ks + 1, cb ^ 1);
            #pragma unroll
            for (int p = 0; p < 4; p++) {
                #pragma unroll
                for (int mt = 0; mt < 4; mt++) {
                    mma_f16(acc[mt][2 * p],     aF[cb][mt], &bF[cb][p][0], &bF[cb][p][1]);
                    mma_f16(acc[mt][2 * p + 1], aF[cb][mt], &bF[cb][p][2], &bF[cb][p][3]);
                }
            }
        }
        __syncthreads();
    }

    // epilogue
    #pragma unroll
    for (int mt = 0; mt < 4; mt++) {
        const int r0 = bm * 256 + wy * 64 + mt * 16 + gid;
        #pragma unroll
        for (int nt = 0; nt < 8; nt++) {
            const int col = bn * 128 + wx * 64 + nt * 8 + tig * 2;
            float2 b2 = *(const float2*)(bias + col);
            float v0 = acc[mt][nt][0] + b2.x;
            float v1 = acc[mt][nt][1] + b2.y;
            float v2 = acc[mt][nt][2] + b2.x;
            float v3 = acc[mt][nt][3] + b2.y;
            if (EP == 1) {
                float2 ra = *(const float2*)(res + (size_t)r0 * Ncols + col);
                float2 rb = *(const float2*)(res + (size_t)(r0 + 8) * Ncols + col);
                v0 += ra.x; v1 += ra.y; v2 += rb.x; v3 += rb.y;
            }
            if (EP == 2) {
                v0 = v0 * (1.f / (1.f + __expf(-v0)));
                v1 = v1 * (1.f / (1.f + __expf(-v1)));
                v2 = v2 * (1.f / (1.f + __expf(-v2)));
                v3 = v3 * (1.f / (1.f + __expf(-v3)));
                *(__half2*)(Ch + (size_t)r0 * Ncols + col) =
                    __floats2half2_rn(v0, v1);
                *(__half2*)(Ch + (size_t)(r0 + 8) * Ncols + col) =
                    __floats2half2_rn(v2, v3);
            } else {
                *(float2*)(C + (size_t)r0 * Ncols + col)       = make_float2(v0, v1);
                *(float2*)(C + (size_t)(r0 + 8) * Ncols + col) = make_float2(v2, v3);
            }
        }
    }
}

// ---------------------------------------------------------------------------
// Weight transpose: in[K][N] fp32 -> out[N][K] fp16
// ---------------------------------------------------------------------------
__global__ void transpose_h(const float* __restrict__ in, __half* __restrict__ out,
                            int K, int N) {
    __shared__ float t[32][33];
    const int bx = blockIdx.x * 32;  // n
    const int by = blockIdx.y * 32;  // k
    const int x = threadIdx.x, y = threadIdx.y;
    #pragma unroll
    for (int i = 0; i < 32; i += 8)
        t[y + i][x] = in[(size_t)(by + y + i) * N + bx + x];
    __syncthreads();
    #pragma unroll
    for (int i = 0; i < 32; i += 8)
        out[(size_t)(bx + y + i) * K + by + x] = __float2half_rn(t[x][y + i]);
}

// ---------------------------------------------------------------------------
// LayerNorm: fp32 in -> fp16 out (feeds GEMMs only)
// ---------------------------------------------------------------------------
__global__ void ln_kernel(const float* __restrict__ x, const float* __restrict__ g,
                          const float* __restrict__ bta, __half* __restrict__ y) {
    const int tid = threadIdx.x;
    const size_t row = blockIdx.x;
    float4 v = ((const float4*)(x + row * DD))[tid];
    __shared__ float red[32];

    float s = v.x + v.y + v.z + v.w;
    #pragma unroll
    for (int o = 16; o; o >>= 1) s += __shfl_xor_sync(0xffffffffu, s, o);
    if ((tid & 31) == 0) red[tid >> 5] = s;
    __syncthreads();
    if (tid < 32) {
        float t = (tid < 8) ? red[tid] : 0.f;
        #pragma unroll
        for (int o = 4; o; o >>= 1) t += __shfl_xor_sync(0xffffffffu, t, o);
        if (tid == 0) red[0] = t;
    }
    __syncthreads();
    const float mean = red[0] * (1.f / DD);

    float dx = v.x - mean, dy = v.y - mean, dz = v.z - mean, dw = v.w - mean;
    float ss = dx * dx + dy * dy + dz * dz + dw * dw;
    #pragma unroll
    for (int o = 16; o; o >>= 1) ss += __shfl_xor_sync(0xffffffffu, ss, o);
    __syncthreads();
    if ((tid & 31) == 0) red[tid >> 5] = ss;
    __syncthreads();
    if (tid < 32) {
        float t = (tid < 8) ? red[tid] : 0.f;
        #pragma unroll
        for (int o = 4; o; o >>= 1) t += __shfl_xor_sync(0xffffffffu, t, o);
        if (tid == 0) red[0] = t;
    }
    __syncthreads();
    const float rstd = rsqrtf(red[0] * (1.f / DD) + EPS_F);

    float4 gg = ((const float4*)g)[tid];
    float4 bb = ((const float4*)bta)[tid];
    __half2* yp = (__half2*)(y + row * DD);
    yp[2 * tid]     = __floats2half2_rn(dx * rstd * gg.x + bb.x,
                                        dy * rstd * gg.y + bb.y);
    yp[2 * tid + 1] = __floats2half2_rn(dz * rstd * gg.z + bb.z,
                                        dw * rstd * gg.w + bb.w);
}

// ---------------------------------------------------------------------------
// softmax stats over N axis of q[B,N,D] per (b, channel): writes M and 1/S
// ---------------------------------------------------------------------------
__global__ void softmax_q_stats(const float* __restrict__ q,
                                float* __restrict__ qM, float* __restrict__ qS) {
    const int b = blockIdx.y;
    const int c = (blockIdx.x << 5) + threadIdx.x;
    const int ty = threadIdx.y;
    const float* base = q + (size_t)b * NN_ * DD + c;

    float m = -1e30f, s = 0.f;
    for (int n = ty; n < NN_; n += 8) {
        float v = base[(size_t)n * DD];
        if (v > m) { s = s * __expf(m - v) + 1.f; m = v; }
        else       { s += __expf(v - m); }
    }
    __shared__ float sm[8][32], ssum[8][32];
    sm[ty][threadIdx.x] = m; ssum[ty][threadIdx.x] = s;
    __syncthreads();
    if (ty == 0) {
        float Mv = -1e30f;
        #pragma unroll
        for (int i = 0; i < 8; i++) Mv = fmaxf(Mv, sm[i][threadIdx.x]);
        float Sv = 0.f;
        #pragma unroll
        for (int i = 0; i < 8; i++)
            Sv += ssum[i][threadIdx.x] * __expf(sm[i][threadIdx.x] - Mv);
        qM[b * DD + c] = Mv;
        qS[b * DD + c] = 1.f / Sv;
    }
}

// softmax over each 64-wide head chunk of k
__global__ void softmax_k_kernel(float* __restrict__ kv) {
    const size_t row = blockIdx.x;
    const int w = threadIdx.x >> 5, lane = threadIdx.x & 31;
    float* p = kv + row * 2048 + w * 64;
    float a = p[lane], c = p[lane + 32];
    float m = fmaxf(a, c);
    #pragma unroll
    for (int o = 16; o; o >>= 1) m = fmaxf(m, __shfl_xor_sync(0xffffffffu, m, o));
    float ea = __expf(a - m), ec = __expf(c - m);
    float s = ea + ec;
    #pragma unroll
    for (int o = 16; o; o >>= 1) s += __shfl_xor_sync(0xffffffffu, s, o);
    const float inv = 1.f / s;
    p[lane] = ea * inv; p[lane + 32] = ec * inv;
}

// context[b,h,:,:] = SCALE * k^T v  (64x64 per head)
__global__ void context_kernel(const float* __restrict__ kv, float* __restrict__ ctx) {
    const int bh = blockIdx.x;
    const int b = bh >> 4, h = bh & 15;
    __shared__ float Ks[64][64];
    __shared__ float Vs[64][64];
    const int tid = threadIdx.x;
    const int tx = tid & 15, ty = tid >> 4;
    const float* kvb = kv + (size_t)b * MM_ * 2048 + h * 64;

    float acc[4][4];
    #pragma unroll
    for (int i = 0; i < 4; i++)
        #pragma unroll
        for (int j = 0; j < 4; j++) acc[i][j] = 0.f;

    for (int m0 = 0; m0 < MM_; m0 += 64) {
        for (int i = tid; i < 1024; i += 256) {
            int r = i >> 4, c4 = (i & 15) << 2;
            const float* rp = kvb + (size_t)(m0 + r) * 2048 + c4;
            *(float4*)&Ks[r][c4] = *(const float4*)rp;
            *(float4*)&Vs[r][c4] = *(const float4*)(rp + 1024);
        }
        __syncthreads();
        #pragma unroll 8
        for (int mm = 0; mm < 64; mm++) {
            float a0 = Ks[mm][ty * 4 + 0], a1 = Ks[mm][ty * 4 + 1];
            float a2 = Ks[mm][ty * 4 + 2], a3 = Ks[mm][ty * 4 + 3];
            float b0 = Vs[mm][tx * 4 + 0], b1 = Vs[mm][tx * 4 + 1];
            float b2 = Vs[mm][tx * 4 + 2], b3 = Vs[mm][tx * 4 + 3];
            acc[0][0] += a0 * b0; acc[0][1] += a0 * b1; acc[0][2] += a0 * b2; acc[0][3] += a0 * b3;
            acc[1][0] += a1 * b0; acc[1][1] += a1 * b1; acc[1][2] += a1 * b2; acc[1][3] += a1 * b3;
            acc[2][0] += a2 * b0; acc[2][1] += a2 * b1; acc[2][2] += a2 * b2; acc[2][3] += a2 * b3;
            acc[3][0] += a3 * b0; acc[3][1] += a3 * b1; acc[3][2] += a3 * b2; acc[3][3] += a3 * b3;
        }
        __syncthreads();
    }
    float* cb = ctx + (size_t)bh * 64 * 64;
    #pragma unroll
    for (int i = 0; i < 4; i++) {
        float o[4];
        #pragma unroll
        for (int j = 0; j < 4; j++) o[j] = acc[i][j] * SCALE_F;
        *(float4*)(cb + (ty * 4 + i) * 64 + tx * 4) = *(float4*)&o[0];
    }
}

// out[b,n,h*64+e] = sum_d softmax_q(q)[b,n,h*64+d] * ctx[b,h,d,e]
// softmax applied on the fly; output fp16 (feeds Wo GEMM)
__global__ void apply_ctx_kernel(const float* __restrict__ q,
                                 const float* __restrict__ qM,
                                 const float* __restrict__ qS,
                                 const float* __restrict__ ctx,
                                 __half* __restrict__ outp) {
    const int bh = blockIdx.y;
    const int b = bh >> 4, h = bh & 15;
    const int n0 = blockIdx.x << 6;
    __shared__ float Cs[64][64];
    __shared__ float Qs[64][64];
    __shared__ float sM[64], sS[64];
    const int tid = threadIdx.x;
    const float* qb = q + ((size_t)(b * NN_ + n0)) * DD + h * 64;
    const float* cb = ctx + (size_t)bh * 64 * 64;

    if (tid < 64) {
        sM[tid] = qM[b * DD + h * 64 + tid];
        sS[tid] = qS[b * DD + h * 64 + tid];
    }
    __syncthreads();

    for (int i = tid; i < 1024; i += 256) {
        int r = i >> 4, c4 = (i & 15) << 2;
        *(float4*)&Cs[r][c4] = *(const float4*)(cb + r * 64 + c4);
        float4 qa = *(const float4*)(qb + (size_t)r * DD + c4);
        qa.x = __expf(qa.x - sM[c4 + 0]) * sS[c4 + 0];
        qa.y = __expf(qa.y - sM[c4 + 1]) * sS[c4 + 1];
        qa.z = __expf(qa.z - sM[c4 + 2]) * sS[c4 + 2];
        qa.w = __expf(qa.w - sM[c4 + 3]) * sS[c4 + 3];
        *(float4*)&Qs[r][c4] = qa;
    }
    __syncthreads();

    const int tx = tid & 15, ty = tid >> 4;
    float acc[4][4];
    #pragma unroll
    for (int i = 0; i < 4; i++)
        #pragma unroll
        for (int j = 0; j < 4; j++) acc[i][j] = 0.f;

    #pragma unroll 8
    for (int d = 0; d < 64; d++) {
        float a0 = Qs[ty * 4 + 0][d], a1 = Qs[ty * 4 + 1][d];
        float a2 = Qs[ty * 4 + 2][d], a3 = Qs[ty * 4 + 3][d];
        float b0 = Cs[d][tx * 4 + 0], b1 = Cs[d][tx * 4 + 1];
        float b2 = Cs[d][tx * 4 + 2], b3 = Cs[d][tx * 4 + 3];
        acc[0][0] += a0 * b0; acc[0][1] += a0 * b1; acc[0][2] += a0 * b2; acc[0][3] += a0 * b3;
        acc[1][0] += a1 * b0; acc[1][1] += a1 * b1; acc[1][2] += a1 * b2; acc[1][3] += a1 * b3;
        acc[2][0] += a2 * b0; acc[2][1] += a2 * b1; acc[2][2] += a2 * b2; acc[2][3] += a2 * b3;
        acc[3][0] += a3 * b0; acc[3][1] += a3 * b1; acc[3][2] += a3 * b2; acc[3][3] += a3 * b3;
    }
    __half* ob = outp + ((size_t)(b * NN_ + n0)) * DD + h * 64;
    #pragma unroll
    for (int i = 0; i < 4; i++) {
        __half2 h01 = __floats2half2_rn(acc[i][0], acc[i][1]);
        __half2 h23 = __floats2half2_rn(acc[i][2], acc[i][3]);
        __half2* op = (__half2*)(ob + (size_t)(ty * 4 + i) * DD + tx * 4);
        op[0] = h01;
        op[1] = h23;
    }
}

// ---------------------------------------------------------------------------
// Launch sequence
// ---------------------------------------------------------------------------
extern "C" void kernel_launch(void* const* d_in, const int* in_sizes, int n_in,
                              void* d_out, int out_size) {
    (void)in_sizes; (void)n_in; (void)out_size;
    const float* x      = (const float*)d_in[0];
    const float* wt     = (const float*)d_in[1];
    const float* ln_q_g = (const float*)d_in[2];
    const float* ln_q_b = (const float*)d_in[3];
    const float* Wq     = (const float*)d_in[4];
    const float* bq     = (const float*)d_in[5];
    const float* ln_kv_g= (const float*)d_in[6];
    const float* ln_kv_b= (const float*)d_in[7];
    const float* Wkv    = (const float*)d_in[8];
    const float* bkv    = (const float*)d_in[9];
    const float* Wo     = (const float*)d_in[10];
    const float* bo     = (const float*)d_in[11];
    const float* ln_f_g = (const float*)d_in[12];
    const float* ln_f_b = (const float*)d_in[13];
    const float* W1     = (const float*)d_in[14];
    const float* b1     = (const float*)d_in[15];
    const float* W2     = (const float*)d_in[16];
    const float* b2     = (const float*)d_in[17];
    float* out = (float*)d_out;

    __half *bufA, *buf1, *WqT, *WkvT, *WoT, *W1T, *W2T;
    float *buf2, *buf3, *kv, *ctx, *qM, *qS;
    cudaGetSymbolAddress((void**)&bufA, g_bufA);
    cudaGetSymbolAddress((void**)&buf1, g_buf1);
    cudaGetSymbolAddress((void**)&buf2, g_buf2);
    cudaGetSymbolAddress((void**)&buf3, g_buf3);
    cudaGetSymbolAddress((void**)&kv,   g_kv);
    cudaGetSymbolAddress((void**)&ctx,  g_ctx);
    cudaGetSymbolAddress((void**)&qM,   g_qM);
    cudaGetSymbolAddress((void**)&qS,   g_qS);
    cudaGetSymbolAddress((void**)&WqT,  g_WqT);
    cudaGetSymbolAddress((void**)&WkvT, g_WkvT);
    cudaGetSymbolAddress((void**)&WoT,  g_WoT);
    cudaGetSymbolAddress((void**)&W1T,  g_W1T);
    cudaGetSymbolAddress((void**)&W2T,  g_W2T);

    cudaFuncSetAttribute(hgemm<0>, cudaFuncAttributeMaxDynamicSharedMemorySize, DSMEM_BYTES);
    cudaFuncSetAttribute(hgemm<1>, cudaFuncAttributeMaxDynamicSharedMemorySize, DSMEM_BYTES);
    cudaFuncSetAttribute(hgemm<2>, cudaFuncAttributeMaxDynamicSharedMemorySize, DSMEM_BYTES);

    // 0. transpose weights -> fp16 [N][K]
    transpose_h<<<dim3(1024 / 32, 1024 / 32), dim3(32, 8)>>>(Wq,  WqT,  1024, 1024);
    transpose_h<<<dim3(2048 / 32, 1024 / 32), dim3(32, 8)>>>(Wkv, WkvT, 1024, 2048);
    transpose_h<<<dim3(1024 / 32, 1024 / 32), dim3(32, 8)>>>(Wo,  WoT,  1024, 1024);
    transpose_h<<<dim3(4096 / 32, 1024 / 32), dim3(32, 8)>>>(W1,  W1T,  1024, 4096);
    transpose_h<<<dim3(1024 / 32, 4096 / 32), dim3(32, 8)>>>(W2,  W2T,  4096, 1024);

    // 1. LN -> fp16
    ln_kernel<<<ROWS_X, 256>>>(x,  ln_q_g,  ln_q_b,  buf1);
    ln_kernel<<<ROWS_W, 256>>>(wt, ln_kv_g, ln_kv_b, bufA);

    // 2. q / kv projections (fp16 mma.sync)
    hgemm<0><<<dim3(DD / 128, ROWS_X / 256), 256, DSMEM_BYTES>>>(
        buf1, WqT, bq, nullptr, buf2, nullptr, DD, DD);
    hgemm<0><<<dim3(2048 / 128, ROWS_W / 256), 256, DSMEM_BYTES>>>(
        bufA, WkvT, bkv, nullptr, kv, nullptr, 2048, DD);

    // 3. softmax stats + linear attention core (q softmax fused into apply)
    softmax_q_stats<<<dim3(DD / 32, BB), dim3(32, 8)>>>(buf2, qM, qS);
    softmax_k_kernel<<<ROWS_W, 512>>>(kv);
    context_kernel<<<BB * HH, 256>>>(kv, ctx);
    apply_ctx_kernel<<<dim3(NN_ / 64, BB * HH), 256>>>(buf2, qM, qS, ctx, buf1);

    // 4. x2 = attn @ Wo + bo + x
    hgemm<1><<<dim3(DD / 128, ROWS_X / 256), 256, DSMEM_BYTES>>>(
        buf1, WoT, bo, x, buf3, nullptr, DD, DD);

    // 5. LN(x2) -> fp16
    ln_kernel<<<ROWS_X, 256>>>(buf3, ln_f_g, ln_f_b, buf1);

    // 6. h = silu(ln2 @ W1 + b1) -> fp16
    hgemm<2><<<dim3(4096 / 128, ROWS_X / 256), 256, DSMEM_BYTES>>>(
        buf1, W1T, b1, nullptr, nullptr, bufA, 4096, DD);

    // 7. out = h @ W2 + b2 + x2
    hgemm<1><<<dim3(DD / 128, ROWS_X / 256), 256, DSMEM_BYTES>>>(
        bufA, W2T, b2, buf3, out, nullptr, DD, 4096);
}

// round 12
// speedup vs baseline: 2.4503x; 1.0323x over previous
#include <cuda_runtime.h>
#include <cuda_fp16.h>
#include <math.h>
#include <stdint.h>

// ---------------------------------------------------------------------------
// Problem constants
// ---------------------------------------------------------------------------
#define BB 8
#define NN_ 4096
#define MM_ 1024
#define DD 1024
#define HH 16
#define SCALE_F 0.125f
#define EPS_F 1e-6f
#define ROWS_X (BB * NN_)   // 32768
#define ROWS_W (BB * MM_)   // 8192

// ---------------------------------------------------------------------------
// Scratch (static device globals)
// ---------------------------------------------------------------------------
__device__ __half g_bufA[(size_t)ROWS_X * 4096]; // lnw (front), then FFN hidden h
__device__ __half g_buf1[(size_t)ROWS_X * DD];   // ln1 -> attn_out -> ln2 (half)
__device__ float  g_buf2[(size_t)ROWS_X * DD];   // q (raw fp32, pre-softmax)
__device__ float  g_buf3[(size_t)ROWS_X * DD];   // x2 (fp32)
__device__ float  g_kv[(size_t)ROWS_W * 2048];
__device__ float  g_ctx[(size_t)BB * HH * 64 * 64];
__device__ float  g_qM[(size_t)BB * DD];
__device__ float  g_qS[(size_t)BB * DD];
// transposed (N,K) weights, fp16
__device__ __half g_WqT[(size_t)1024 * 1024];
__device__ __half g_WkvT[(size_t)2048 * 1024];
__device__ __half g_WoT[(size_t)1024 * 1024];
__device__ __half g_W1T[(size_t)4096 * 1024];
__device__ __half g_W2T[(size_t)1024 * 4096];

// ---------------------------------------------------------------------------
// Helpers
// ---------------------------------------------------------------------------
__device__ __forceinline__ uint32_t smem_u32(const void* p) {
    uint32_t a;
    asm("{ .reg .u64 t; cvta.to.shared.u64 t, %1; cvt.u32.u64 %0, t; }"
        : "=r"(a) : "l"(p));
    return a;
}

__device__ __forceinline__ void cp_async16(uint32_t smem, const void* gmem) {
    asm volatile("cp.async.cg.shared.global [%0], [%1], 16;\n"
                 :: "r"(smem), "l"(gmem));
}
#define CP_COMMIT() asm volatile("cp.async.commit_group;" ::: "memory")

// ldmatrix x4: four 8x8 b16 tiles, per-lane addresses
__device__ __forceinline__ void ldsm_x4(uint32_t* r, uint32_t addr) {
    asm volatile("ldmatrix.sync.aligned.m8n8.x4.shared.b16 {%0,%1,%2,%3}, [%4];"
                 : "=r"(r[0]), "=r"(r[1]), "=r"(r[2]), "=r"(r[3]) : "r"(addr));
}

// m16n8k16 fp16 MMA with fp32 accumulate (sm_80+, arch-portable)
__device__ __forceinline__ void mma_f16(float* d, const uint32_t* a,
                                        const uint32_t* b0, const uint32_t* b1) {
    asm volatile(
        "mma.sync.aligned.m16n8k16.row.col.f32.f16.f16.f32 "
        "{%0,%1,%2,%3}, {%4,%5,%6,%7}, {%8,%9}, {%0,%1,%2,%3};"
        : "+f"(d[0]), "+f"(d[1]), "+f"(d[2]), "+f"(d[3])
        : "r"(a[0]), "r"(a[1]), "r"(a[2]), "r"(a[3]), "r"(*b0), "r"(*b1));
}

// ---------------------------------------------------------------------------
// fp16 mma.sync GEMM: C[M,N] = A[M,K] @ BT[N,K]^T + bias (+variants)
// CTA tile 256x128, 8 warps (4x2), warp tile 64x64, K-chunk=64 (4 x k16),
// 4-stage cp.async pipeline, ldmatrix operand loads, fragment double-buffer.
// EP: 0 = +bias -> fp32 ; 1 = +bias +res -> fp32 ; 2 = silu(+bias) -> half
//     3 = +bias, then per-64-col-chunk softmax for bn<8 (k half) -> fp32
// ---------------------------------------------------------------------------
#define A_STAGE_BYTES 32768u       // 256 rows x 64 k x 2B
#define B_STAGE_BYTES 16384u       // 128 rows x 64 k x 2B
#define STAGE_BYTES (A_STAGE_BYTES + B_STAGE_BYTES)
#define NSTAGE 4
#define DSMEM_BYTES (NSTAGE * STAGE_BYTES)

template <int EP>
__global__ void __launch_bounds__(256)
hgemm(const __half* __restrict__ A, const __half* __restrict__ BT,
      const float* __restrict__ bias, const float* __restrict__ res,
      float* __restrict__ C, __half* __restrict__ Ch, int Ncols, int K) {
    extern __shared__ char dsm[];
    const uint32_t smem0 = smem_u32(dsm);

    const int tid = threadIdx.x;
    const int lane = tid & 31, warp = tid >> 5;
    const int wy = warp >> 1, wx = warp & 1;        // 4x2 warp grid
    const int gid = lane >> 2, tig = lane & 3;      // mma fragment coords
    const int bm = blockIdx.y, bn = blockIdx.x;

    const __half* Abase = A + (size_t)(bm * 256) * K;
    const __half* Bbase = BT + (size_t)(bn * 128) * K;
    const int ntiles = K >> 6;                      // 64 k per chunk

    // per-lane ldmatrix row/unit decomposition
    const int laneA_r = wy * 64 + ((lane >> 3) & 1) * 8 + (lane & 7);
    const int laneA_u = lane >> 4;
    const int laneA_s7 = laneA_r & 7;
    const int laneB_r = wx * 64 + (lane >> 4) * 8 + (lane & 7);
    const int laneB_u = (lane >> 3) & 1;
    const int laneB_s7 = laneB_r & 7;

    float acc[4][8][4];
    #pragma unroll
    for (int mt = 0; mt < 4; mt++)
        #pragma unroll
        for (int nt = 0; nt < 8; nt++)
            #pragma unroll
            for (int r = 0; r < 4; r++) acc[mt][nt][r] = 0.f;

    auto load_chunk = [&](int c) {
        const uint32_t so = smem0 + (uint32_t)(c % NSTAGE) * STAGE_BYTES;
        const int k0 = c << 6;
        #pragma unroll
        for (int t = 0; t < 8; t++) {
            const int i = tid + t * 256;
            const int r = i >> 3, u = i & 7;
            const uint32_t du = (uint32_t)((u ^ (r & 7)) << 4);
            cp_async16(so + (uint32_t)(r * 128) + du,
                       Abase + (size_t)r * K + k0 + u * 8);
        }
        #pragma unroll
        for (int t = 0; t < 4; t++) {
            const int i = tid + t * 256;
            const int r = i >> 3, u = i & 7;
            const uint32_t du = (uint32_t)((u ^ (r & 7)) << 4);
            cp_async16(so + A_STAGE_BYTES + (uint32_t)(r * 128) + du,
                       Bbase + (size_t)r * K + k0 + u * 8);
        }
        CP_COMMIT();
    };

    load_chunk(0);
    load_chunk(1);
    load_chunk(2);

    uint32_t aF[2][4][4];
    uint32_t bF[2][4][4];

    auto load_frags = [&](uint32_t sA, uint32_t sB, int ks, int buf) {
        const uint32_t uA = (uint32_t)(((ks * 2 + laneA_u) ^ laneA_s7) << 4);
        #pragma unroll
        for (int mt = 0; mt < 4; mt++)
            ldsm_x4(aF[buf][mt],
                    sA + (uint32_t)((laneA_r + mt * 16) * 128) + uA);
        const uint32_t uB = (uint32_t)(((ks * 2 + laneB_u) ^ laneB_s7) << 4);
        #pragma unroll
        for (int p = 0; p < 4; p++)
            ldsm_x4(bF[buf][p],
                    sB + (uint32_t)((laneB_r + p * 16) * 128) + uB);
    };

    for (int c = 0; c < ntiles; c++) {
        asm volatile("cp.async.wait_group 2;" ::: "memory");
        __syncthreads();

        const uint32_t sA = smem0 + (uint32_t)(c % NSTAGE) * STAGE_BYTES;
        const uint32_t sB = sA + A_STAGE_BYTES;

        load_frags(sA, sB, 0, 0);

        if (c + 3 < ntiles) load_chunk(c + 3);
        else CP_COMMIT();

        #pragma unroll
        for (int ks = 0; ks < 4; ks++) {
            const int cb = ks & 1;
            if (ks < 3) load_frags(sA, sB, ks + 1, cb ^ 1);
            #pragma unroll
            for (int p = 0; p < 4; p++) {
                #pragma unroll
                for (int mt = 0; mt < 4; mt++) {
                    mma_f16(acc[mt][2 * p],     aF[cb][mt], &bF[cb][p][0], &bF[cb][p][1]);
                    mma_f16(acc[mt][2 * p + 1], aF[cb][mt], &bF[cb][p][2], &bF[cb][p][3]);
                }
            }
        }
        __syncthreads();
    }

    // epilogue
    if (EP == 3) {
        // kv projection: +bias, then softmax over the warp's 64-col chunk
        // (one attention head) for the k half (bn < 8). Quad (4 lanes, same
        // row) holds the full 64-col chunk for rows r0 and r0+8.
        const bool do_soft = (bn < 8);
        #pragma unroll
        for (int mt = 0; mt < 4; mt++) {
            const int r0 = bm * 256 + wy * 64 + mt * 16 + gid;
            float m01 = -1e30f, m23 = -1e30f;
            #pragma unroll
            for (int nt = 0; nt < 8; nt++) {
                const int col = bn * 128 + wx * 64 + nt * 8 + tig * 2;
                float2 b2 = *(const float2*)(bias + col);
                acc[mt][nt][0] += b2.x; acc[mt][nt][1] += b2.y;
                acc[mt][nt][2] += b2.x; acc[mt][nt][3] += b2.y;
                m01 = fmaxf(m01, fmaxf(acc[mt][nt][0], acc[mt][nt][1]));
                m23 = fmaxf(m23, fmaxf(acc[mt][nt][2], acc[mt][nt][3]));
            }
            if (do_soft) {
                m01 = fmaxf(m01, __shfl_xor_sync(0xffffffffu, m01, 1));
                m01 = fmaxf(m01, __shfl_xor_sync(0xffffffffu, m01, 2));
                m23 = fmaxf(m23, __shfl_xor_sync(0xffffffffu, m23, 1));
                m23 = fmaxf(m23, __shfl_xor_sync(0xffffffffu, m23, 2));
                float s01 = 0.f, s23 = 0.f;
                #pragma unroll
                for (int nt = 0; nt < 8; nt++) {
                    acc[mt][nt][0] = __expf(acc[mt][nt][0] - m01);
                    acc[mt][nt][1] = __expf(acc[mt][nt][1] - m01);
                    acc[mt][nt][2] = __expf(acc[mt][nt][2] - m23);
                    acc[mt][nt][3] = __expf(acc[mt][nt][3] - m23);
                    s01 += acc[mt][nt][0] + acc[mt][nt][1];
                    s23 += acc[mt][nt][2] + acc[mt][nt][3];
                }
                s01 += __shfl_xor_sync(0xffffffffu, s01, 1);
                s01 += __shfl_xor_sync(0xffffffffu, s01, 2);
                s23 += __shfl_xor_sync(0xffffffffu, s23, 1);
                s23 += __shfl_xor_sync(0xffffffffu, s23, 2);
                const float i01 = 1.f / s01, i23 = 1.f / s23;
                #pragma unroll
                for (int nt = 0; nt < 8; nt++) {
                    acc[mt][nt][0] *= i01; acc[mt][nt][1] *= i01;
                    acc[mt][nt][2] *= i23; acc[mt][nt][3] *= i23;
                }
            }
            #pragma unroll
            for (int nt = 0; nt < 8; nt++) {
                const int col = bn * 128 + wx * 64 + nt * 8 + tig * 2;
                *(float2*)(C + (size_t)r0 * Ncols + col) =
                    make_float2(acc[mt][nt][0], acc[mt][nt][1]);
                *(float2*)(C + (size_t)(r0 + 8) * Ncols + col) =
                    make_float2(acc[mt][nt][2], acc[mt][nt][3]);
            }
        }
    } else {
        #pragma unroll
        for (int mt = 0; mt < 4; mt++) {
            const int r0 = bm * 256 + wy * 64 + mt * 16 + gid;
            #pragma unroll
            for (int nt = 0; nt < 8; nt++) {
                const int col = bn * 128 + wx * 64 + nt * 8 + tig * 2;
                float2 b2 = *(const float2*)(bias + col);
                float v0 = acc[mt][nt][0] + b2.x;
                float v1 = acc[mt][nt][1] + b2.y;
                float v2 = acc[mt][nt][2] + b2.x;
                float v3 = acc[mt][nt][3] + b2.y;
                if (EP == 1) {
                    float2 ra = *(const float2*)(res + (size_t)r0 * Ncols + col);
                    float2 rb = *(const float2*)(res + (size_t)(r0 + 8) * Ncols + col);
                    v0 += ra.x; v1 += ra.y; v2 += rb.x; v3 += rb.y;
                }
                if (EP == 2) {
                    v0 = v0 * (1.f / (1.f + __expf(-v0)));
                    v1 = v1 * (1.f / (1.f + __expf(-v1)));
                    v2 = v2 * (1.f / (1.f + __expf(-v2)));
                    v3 = v3 * (1.f / (1.f + __expf(-v3)));
                    *(__half2*)(Ch + (size_t)r0 * Ncols + col) =
                        __floats2half2_rn(v0, v1);
                    *(__half2*)(Ch + (size_t)(r0 + 8) * Ncols + col) =
                        __floats2half2_rn(v2, v3);
                } else {
                    *(float2*)(C + (size_t)r0 * Ncols + col)       = make_float2(v0, v1);
                    *(float2*)(C + (size_t)(r0 + 8) * Ncols + col) = make_float2(v2, v3);
                }
            }
        }
    }
}

// ---------------------------------------------------------------------------
// Weight transpose: in[K][N] fp32 -> out[N][K] fp16
// ---------------------------------------------------------------------------
__global__ void transpose_h(const float* __restrict__ in, __half* __restrict__ out,
                            int K, int N) {
    __shared__ float t[32][33];
    const int bx = blockIdx.x * 32;  // n
    const int by = blockIdx.y * 32;  // k
    const int x = threadIdx.x, y = threadIdx.y;
    #pragma unroll
    for (int i = 0; i < 32; i += 8)
        t[y + i][x] = in[(size_t)(by + y + i) * N + bx + x];
    __syncthreads();
    #pragma unroll
    for (int i = 0; i < 32; i += 8)
        out[(size_t)(bx + y + i) * K + by + x] = __float2half_rn(t[x][y + i]);
}

// ---------------------------------------------------------------------------
// LayerNorm: fp32 in -> fp16 out (feeds GEMMs only)
// ---------------------------------------------------------------------------
__global__ void ln_kernel(const float* __restrict__ x, const float* __restrict__ g,
                          const float* __restrict__ bta, __half* __restrict__ y) {
    const int tid = threadIdx.x;
    const size_t row = blockIdx.x;
    float4 v = ((const float4*)(x + row * DD))[tid];
    __shared__ float red[32];

    float s = v.x + v.y + v.z + v.w;
    #pragma unroll
    for (int o = 16; o; o >>= 1) s += __shfl_xor_sync(0xffffffffu, s, o);
    if ((tid & 31) == 0) red[tid >> 5] = s;
    __syncthreads();
    if (tid < 32) {
        float t = (tid < 8) ? red[tid] : 0.f;
        #pragma unroll
        for (int o = 4; o; o >>= 1) t += __shfl_xor_sync(0xffffffffu, t, o);
        if (tid == 0) red[0] = t;
    }
    __syncthreads();
    const float mean = red[0] * (1.f / DD);

    float dx = v.x - mean, dy = v.y - mean, dz = v.z - mean, dw = v.w - mean;
    float ss = dx * dx + dy * dy + dz * dz + dw * dw;
    #pragma unroll
    for (int o = 16; o; o >>= 1) ss += __shfl_xor_sync(0xffffffffu, ss, o);
    __syncthreads();
    if ((tid & 31) == 0) red[tid >> 5] = ss;
    __syncthreads();
    if (tid < 32) {
        float t = (tid < 8) ? red[tid] : 0.f;
        #pragma unroll
        for (int o = 4; o; o >>= 1) t += __shfl_xor_sync(0xffffffffu, t, o);
        if (tid == 0) red[0] = t;
    }
    __syncthreads();
    const float rstd = rsqrtf(red[0] * (1.f / DD) + EPS_F);

    float4 gg = ((const float4*)g)[tid];
    float4 bb = ((const float4*)bta)[tid];
    __half2* yp = (__half2*)(y + row * DD);
    yp[2 * tid]     = __floats2half2_rn(dx * rstd * gg.x + bb.x,
                                        dy * rstd * gg.y + bb.y);
    yp[2 * tid + 1] = __floats2half2_rn(dz * rstd * gg.z + bb.z,
                                        dw * rstd * gg.w + bb.w);
}

// ---------------------------------------------------------------------------
// softmax stats over N axis of q[B,N,D] per (b, channel): writes M and 1/S
// ---------------------------------------------------------------------------
__global__ void softmax_q_stats(const float* __restrict__ q,
                                float* __restrict__ qM, float* __restrict__ qS) {
    const int b = blockIdx.y;
    const int c = (blockIdx.x << 5) + threadIdx.x;
    const int ty = threadIdx.y;
    const float* base = q + (size_t)b * NN_ * DD + c;

    float m = -1e30f, s = 0.f;
    for (int n = ty; n < NN_; n += 8) {
        float v = base[(size_t)n * DD];
        if (v > m) { s = s * __expf(m - v) + 1.f; m = v; }
        else       { s += __expf(v - m); }
    }
    __shared__ float sm[8][32], ssum[8][32];
    sm[ty][threadIdx.x] = m; ssum[ty][threadIdx.x] = s;
    __syncthreads();
    if (ty == 0) {
        float Mv = -1e30f;
        #pragma unroll
        for (int i = 0; i < 8; i++) Mv = fmaxf(Mv, sm[i][threadIdx.x]);
        float Sv = 0.f;
        #pragma unroll
        for (int i = 0; i < 8; i++)
            Sv += ssum[i][threadIdx.x] * __expf(sm[i][threadIdx.x] - Mv);
        qM[b * DD + c] = Mv;
        qS[b * DD + c] = 1.f / Sv;
    }
}

// context[b,h,:,:] = SCALE * k^T v  (64x64 per head); kv already softmaxed (k half)
__global__ void context_kernel(const float* __restrict__ kv, float* __restrict__ ctx) {
    const int bh = blockIdx.x;
    const int b = bh >> 4, h = bh & 15;
    __shared__ float Ks[64][64];
    __shared__ float Vs[64][64];
    const int tid = threadIdx.x;
    const int tx = tid & 15, ty = tid >> 4;
    const float* kvb = kv + (size_t)b * MM_ * 2048 + h * 64;

    float acc[4][4];
    #pragma unroll
    for (int i = 0; i < 4; i++)
        #pragma unroll
        for (int j = 0; j < 4; j++) acc[i][j] = 0.f;

    for (int m0 = 0; m0 < MM_; m0 += 64) {
        for (int i = tid; i < 1024; i += 256) {
            int r = i >> 4, c4 = (i & 15) << 2;
            const float* rp = kvb + (size_t)(m0 + r) * 2048 + c4;
            *(float4*)&Ks[r][c4] = *(const float4*)rp;
            *(float4*)&Vs[r][c4] = *(const float4*)(rp + 1024);
        }
        __syncthreads();
        #pragma unroll 8
        for (int mm = 0; mm < 64; mm++) {
            float a0 = Ks[mm][ty * 4 + 0], a1 = Ks[mm][ty * 4 + 1];
            float a2 = Ks[mm][ty * 4 + 2], a3 = Ks[mm][ty * 4 + 3];
            float b0 = Vs[mm][tx * 4 + 0], b1 = Vs[mm][tx * 4 + 1];
            float b2 = Vs[mm][tx * 4 + 2], b3 = Vs[mm][tx * 4 + 3];
            acc[0][0] += a0 * b0; acc[0][1] += a0 * b1; acc[0][2] += a0 * b2; acc[0][3] += a0 * b3;
            acc[1][0] += a1 * b0; acc[1][1] += a1 * b1; acc[1][2] += a1 * b2; acc[1][3] += a1 * b3;
            acc[2][0] += a2 * b0; acc[2][1] += a2 * b1; acc[2][2] += a2 * b2; acc[2][3] += a2 * b3;
            acc[3][0] += a3 * b0; acc[3][1] += a3 * b1; acc[3][2] += a3 * b2; acc[3][3] += a3 * b3;
        }
        __syncthreads();
    }
    float* cb = ctx + (size_t)bh * 64 * 64;
    #pragma unroll
    for (int i = 0; i < 4; i++) {
        float o[4];
        #pragma unroll
        for (int j = 0; j < 4; j++) o[j] = acc[i][j] * SCALE_F;
        *(float4*)(cb + (ty * 4 + i) * 64 + tx * 4) = *(float4*)&o[0];
    }
}

// out[b,n,h*64+e] = sum_d softmax_q(q)[b,n,h*64+d] * ctx[b,h,d,e]
__global__ void apply_ctx_kernel(const float* __restrict__ q,
                                 const float* __restrict__ qM,
                                 const float* __restrict__ qS,
                                 const float* __restrict__ ctx,
                                 __half* __restrict__ outp) {
    const int bh = blockIdx.y;
    const int b = bh >> 4, h = bh & 15;
    const int n0 = blockIdx.x << 6;
    __shared__ float Cs[64][64];
    __shared__ float Qs[64][64];
    __shared__ float sM[64], sS[64];
    const int tid = threadIdx.x;
    const float* qb = q + ((size_t)(b * NN_ + n0)) * DD + h * 64;
    const float* cb = ctx + (size_t)bh * 64 * 64;

    if (tid < 64) {
        sM[tid] = qM[b * DD + h * 64 + tid];
        sS[tid] = qS[b * DD + h * 64 + tid];
    }
    __syncthreads();

    for (int i = tid; i < 1024; i += 256) {
        int r = i >> 4, c4 = (i & 15) << 2;
        *(float4*)&Cs[r][c4] = *(const float4*)(cb + r * 64 + c4);
        float4 qa = *(const float4*)(qb + (size_t)r * DD + c4);
        qa.x = __expf(qa.x - sM[c4 + 0]) * sS[c4 + 0];
        qa.y = __expf(qa.y - sM[c4 + 1]) * sS[c4 + 1];
        qa.z = __expf(qa.z - sM[c4 + 2]) * sS[c4 + 2];
        qa.w = __expf(qa.w - sM[c4 + 3]) * sS[c4 + 3];
        *(float4*)&Qs[r][c4] = qa;
    }
    __syncthreads();

    const int tx = tid & 15, ty = tid >> 4;
    float acc[4][4];
    #pragma unroll
    for (int i = 0; i < 4; i++)
        #pragma unroll
        for (int j = 0; j < 4; j++) acc[i][j] = 0.f;

    #pragma unroll 8
    for (int d = 0; d < 64; d++) {
        float a0 = Qs[ty * 4 + 0][d], a1 = Qs[ty * 4 + 1][d];
        float a2 = Qs[ty * 4 + 2][d], a3 = Qs[ty * 4 + 3][d];
        float b0 = Cs[d][tx * 4 + 0], b1 = Cs[d][tx * 4 + 1];
        float b2 = Cs[d][tx * 4 + 2], b3 = Cs[d][tx * 4 + 3];
        acc[0][0] += a0 * b0; acc[0][1] += a0 * b1; acc[0][2] += a0 * b2; acc[0][3] += a0 * b3;
        acc[1][0] += a1 * b0; acc[1][1] += a1 * b1; acc[1][2] += a1 * b2; acc[1][3] += a1 * b3;
        acc[2][0] += a2 * b0; acc[2][1] += a2 * b1; acc[2][2] += a2 * b2; acc[2][3] += a2 * b3;
        acc[3][0] += a3 * b0; acc[3][1] += a3 * b1; acc[3][2] += a3 * b2; acc[3][3] += a3 * b3;
    }
    __half* ob = outp + ((size_t)(b * NN_ + n0)) * DD + h * 64;
    #pragma unroll
    for (int i = 0; i < 4; i++) {
        __half2 h01 = __floats2half2_rn(acc[i][0], acc[i][1]);
        __half2 h23 = __floats2half2_rn(acc[i][2], acc[i][3]);
        __half2* op = (__half2*)(ob + (size_t)(ty * 4 + i) * DD + tx * 4);
        op[0] = h01;
        op[1] = h23;
    }
}

// ---------------------------------------------------------------------------
// Launch sequence: multi-stream fork/join DAG (graph-capture safe)
// ---------------------------------------------------------------------------
extern "C" void kernel_launch(void* const* d_in, const int* in_sizes, int n_in,
                              void* d_out, int out_size) {
    (void)in_sizes; (void)n_in; (void)out_size;
    const float* x      = (const float*)d_in[0];
    const float* wt     = (const float*)d_in[1];
    const float* ln_q_g = (const float*)d_in[2];
    const float* ln_q_b = (const float*)d_in[3];
    const float* Wq     = (const float*)d_in[4];
    const float* bq     = (const float*)d_in[5];
    const float* ln_kv_g= (const float*)d_in[6];
    const float* ln_kv_b= (const float*)d_in[7];
    const float* Wkv    = (const float*)d_in[8];
    const float* bkv    = (const float*)d_in[9];
    const float* Wo     = (const float*)d_in[10];
    const float* bo     = (const float*)d_in[11];
    const float* ln_f_g = (const float*)d_in[12];
    const float* ln_f_b = (const float*)d_in[13];
    const float* W1     = (const float*)d_in[14];
    const float* b1     = (const float*)d_in[15];
    const float* W2     = (const float*)d_in[16];
    const float* b2     = (const float*)d_in[17];
    float* out = (float*)d_out;

    __half *bufA, *buf1, *WqT, *WkvT, *WoT, *W1T, *W2T;
    float *buf2, *buf3, *kv, *ctx, *qM, *qS;
    cudaGetSymbolAddress((void**)&bufA, g_bufA);
    cudaGetSymbolAddress((void**)&buf1, g_buf1);
    cudaGetSymbolAddress((void**)&buf2, g_buf2);
    cudaGetSymbolAddress((void**)&buf3, g_buf3);
    cudaGetSymbolAddress((void**)&kv,   g_kv);
    cudaGetSymbolAddress((void**)&ctx,  g_ctx);
    cudaGetSymbolAddress((void**)&qM,   g_qM);
    cudaGetSymbolAddress((void**)&qS,   g_qS);
    cudaGetSymbolAddress((void**)&WqT,  g_WqT);
    cudaGetSymbolAddress((void**)&WkvT, g_WkvT);
    cudaGetSymbolAddress((void**)&WoT,  g_WoT);
    cudaGetSymbolAddress((void**)&W1T,  g_W1T);
    cudaGetSymbolAddress((void**)&W2T,  g_W2T);

    cudaFuncSetAttribute(hgemm<0>, cudaFuncAttributeMaxDynamicSharedMemorySize, DSMEM_BYTES);
    cudaFuncSetAttribute(hgemm<1>, cudaFuncAttributeMaxDynamicSharedMemorySize, DSMEM_BYTES);
    cudaFuncSetAttribute(hgemm<2>, cudaFuncAttributeMaxDynamicSharedMemorySize, DSMEM_BYTES);
    cudaFuncSetAttribute(hgemm<3>, cudaFuncAttributeMaxDynamicSharedMemorySize, DSMEM_BYTES);

    // one-time host objects (no device memory; same captured work every call)
    static cudaStream_t sW = nullptr, sB = nullptr;
    static cudaEvent_t evRoot, evWq, evWkv, evWo, evW1, evW2, evKv;
    if (sW == nullptr) {
        cudaStreamCreateWithFlags(&sW, cudaStreamNonBlocking);
        cudaStreamCreateWithFlags(&sB, cudaStreamNonBlocking);
        cudaEventCreateWithFlags(&evRoot, cudaEventDisableTiming);
        cudaEventCreateWithFlags(&evWq,   cudaEventDisableTiming);
        cudaEventCreateWithFlags(&evWkv,  cudaEventDisableTiming);
        cudaEventCreateWithFlags(&evWo,   cudaEventDisableTiming);
        cudaEventCreateWithFlags(&evW1,   cudaEventDisableTiming);
        cudaEventCreateWithFlags(&evW2,   cudaEventDisableTiming);
        cudaEventCreateWithFlags(&evKv,   cudaEventDisableTiming);
    }

    // fork
    cudaEventRecord(evRoot, 0);
    cudaStreamWaitEvent(sW, evRoot, 0);
    cudaStreamWaitEvent(sB, evRoot, 0);

    // stream W: weight transposes
    transpose_h<<<dim3(1024 / 32, 1024 / 32), dim3(32, 8), 0, sW>>>(Wq, WqT, 1024, 1024);
    cudaEventRecord(evWq, sW);
    transpose_h<<<dim3(2048 / 32, 1024 / 32), dim3(32, 8), 0, sW>>>(Wkv, WkvT, 1024, 2048);
    cudaEventRecord(evWkv, sW);
    transpose_h<<<dim3(1024 / 32, 1024 / 32), dim3(32, 8), 0, sW>>>(Wo, WoT, 1024, 1024);
    cudaEventRecord(evWo, sW);
    transpose_h<<<dim3(4096 / 32, 1024 / 32), dim3(32, 8), 0, sW>>>(W1, W1T, 1024, 4096);
    cudaEventRecord(evW1, sW);
    transpose_h<<<dim3(1024 / 32, 4096 / 32), dim3(32, 8), 0, sW>>>(W2, W2T, 4096, 1024);
    cudaEventRecord(evW2, sW);

    // stream B: kv chain (LN(w) -> kv GEMM w/ fused softmax_k -> context)
    ln_kernel<<<ROWS_W, 256, 0, sB>>>(wt, ln_kv_g, ln_kv_b, bufA);
    cudaStreamWaitEvent(sB, evWkv, 0);
    hgemm<3><<<dim3(2048 / 128, ROWS_W / 256), 256, DSMEM_BYTES, sB>>>(
        bufA, WkvT, bkv, nullptr, kv, nullptr, 2048, DD);
    context_kernel<<<BB * HH, 256, 0, sB>>>(kv, ctx);
    cudaEventRecord(evKv, sB);

    // stream 0: q chain
    ln_kernel<<<ROWS_X, 256>>>(x, ln_q_g, ln_q_b, buf1);
    cudaStreamWaitEvent(0, evWq, 0);
    hgemm<0><<<dim3(DD / 128, ROWS_X / 256), 256, DSMEM_BYTES>>>(
        buf1, WqT, bq, nullptr, buf2, nullptr, DD, DD);
    softmax_q_stats<<<dim3(DD / 32, BB), dim3(32, 8)>>>(buf2, qM, qS);

    // join kv chain, then apply
    cudaStreamWaitEvent(0, evKv, 0);
    apply_ctx_kernel<<<dim3(NN_ / 64, BB * HH), 256>>>(buf2, qM, qS, ctx, buf1);

    // x2 = attn @ Wo + bo + x
    cudaStreamWaitEvent(0, evWo, 0);
    hgemm<1><<<dim3(DD / 128, ROWS_X / 256), 256, DSMEM_BYTES>>>(
        buf1, WoT, bo, x, buf3, nullptr, DD, DD);

    // LN(x2) -> fp16
    ln_kernel<<<ROWS_X, 256>>>(buf3, ln_f_g, ln_f_b, buf1);

    // h = silu(ln2 @ W1 + b1) -> fp16
    cudaStreamWaitEvent(0, evW1, 0);
    hgemm<2><<<dim3(4096 / 128, ROWS_X / 256), 256, DSMEM_BYTES>>>(
        buf1, W1T, b1, nullptr, nullptr, bufA, 4096, DD);

    // out = h @ W2 + b2 + x2   (joins stream W's tail via evW2)
    cudaStreamWaitEvent(0, evW2, 0);
    hgemm<1><<<dim3(DD / 128, ROWS_X / 256), 256, DSMEM_BYTES>>>(
        bufA, W2T, b2, buf3, out, nullptr, DD, 4096);
}

// round 13
// speedup vs baseline: 2.4806x; 1.0123x over previous
#include <cuda_runtime.h>
#include <cuda_fp16.h>
#include <math.h>
#include <stdint.h>

// ---------------------------------------------------------------------------
// Problem constants
// ---------------------------------------------------------------------------
#define BB 8
#define NN_ 4096
#define MM_ 1024
#define DD 1024
#define HH 16
#define SCALE_F 0.125f
#define EPS_F 1e-6f
#define ROWS_X (BB * NN_)   // 32768
#define ROWS_W (BB * MM_)   // 8192
#define GROUP_ROWS (ROWS_X / 2)   // 16384 rows per M-group (4 batches)

// ---------------------------------------------------------------------------
// Scratch (static device globals)
// ---------------------------------------------------------------------------
__device__ __half g_bufA[(size_t)ROWS_X * 4096]; // lnw (front), then FFN hidden h
__device__ __half g_buf1[(size_t)ROWS_X * DD];   // ln1 -> attn_out -> ln2 (half)
__device__ float  g_buf2[(size_t)ROWS_X * DD];   // q (raw fp32, pre-softmax)
__device__ float  g_buf3[(size_t)ROWS_X * DD];   // x2 (fp32)
__device__ float  g_kv[(size_t)ROWS_W * 2048];
__device__ float  g_ctx[(size_t)BB * HH * 64 * 64];
__device__ float  g_qM[(size_t)BB * DD];
__device__ float  g_qS[(size_t)BB * DD];
// transposed (N,K) weights, fp16
__device__ __half g_WqT[(size_t)1024 * 1024];
__device__ __half g_WkvT[(size_t)2048 * 1024];
__device__ __half g_WoT[(size_t)1024 * 1024];
__device__ __half g_W1T[(size_t)4096 * 1024];
__device__ __half g_W2T[(size_t)1024 * 4096];

// ---------------------------------------------------------------------------
// Helpers
// ---------------------------------------------------------------------------
__device__ __forceinline__ uint32_t smem_u32(const void* p) {
    uint32_t a;
    asm("{ .reg .u64 t; cvta.to.shared.u64 t, %1; cvt.u32.u64 %0, t; }"
        : "=r"(a) : "l"(p));
    return a;
}

__device__ __forceinline__ void cp_async16(uint32_t smem, const void* gmem) {
    asm volatile("cp.async.cg.shared.global [%0], [%1], 16;\n"
                 :: "r"(smem), "l"(gmem));
}
#define CP_COMMIT() asm volatile("cp.async.commit_group;" ::: "memory")

// ldmatrix x4: four 8x8 b16 tiles, per-lane addresses
__device__ __forceinline__ void ldsm_x4(uint32_t* r, uint32_t addr) {
    asm volatile("ldmatrix.sync.aligned.m8n8.x4.shared.b16 {%0,%1,%2,%3}, [%4];"
                 : "=r"(r[0]), "=r"(r[1]), "=r"(r[2]), "=r"(r[3]) : "r"(addr));
}

// m16n8k16 fp16 MMA with fp32 accumulate (sm_80+, arch-portable)
__device__ __forceinline__ void mma_f16(float* d, const uint32_t* a,
                                        const uint32_t* b0, const uint32_t* b1) {
    asm volatile(
        "mma.sync.aligned.m16n8k16.row.col.f32.f16.f16.f32 "
        "{%0,%1,%2,%3}, {%4,%5,%6,%7}, {%8,%9}, {%0,%1,%2,%3};"
        : "+f"(d[0]), "+f"(d[1]), "+f"(d[2]), "+f"(d[3])
        : "r"(a[0]), "r"(a[1]), "r"(a[2]), "r"(a[3]), "r"(*b0), "r"(*b1));
}

// ---------------------------------------------------------------------------
// fp16 mma.sync GEMM: C[M,N] = A[M,K] @ BT[N,K]^T + bias (+variants)
// CTA tile 256x128, 8 warps (4x2), warp tile 64x64, K-chunk=64 (4 x k16),
// 4-stage cp.async pipeline, ldmatrix operand loads, fragment double-buffer.
// EP: 0 = +bias -> fp32 ; 1 = +bias +res -> fp32 ; 2 = silu(+bias) -> half
//     3 = +bias, then per-64-col-chunk softmax for bn<8 (k half) -> fp32
// ---------------------------------------------------------------------------
#define A_STAGE_BYTES 32768u       // 256 rows x 64 k x 2B
#define B_STAGE_BYTES 16384u       // 128 rows x 64 k x 2B
#define STAGE_BYTES (A_STAGE_BYTES + B_STAGE_BYTES)
#define NSTAGE 4
#define DSMEM_BYTES (NSTAGE * STAGE_BYTES)

template <int EP>
__global__ void __launch_bounds__(256)
hgemm(const __half* __restrict__ A, const __half* __restrict__ BT,
      const float* __restrict__ bias, const float* __restrict__ res,
      float* __restrict__ C, __half* __restrict__ Ch, int Ncols, int K) {
    extern __shared__ char dsm[];
    const uint32_t smem0 = smem_u32(dsm);

    const int tid = threadIdx.x;
    const int lane = tid & 31, warp = tid >> 5;
    const int wy = warp >> 1, wx = warp & 1;        // 4x2 warp grid
    const int gid = lane >> 2, tig = lane & 3;      // mma fragment coords
    const int bm = blockIdx.y, bn = blockIdx.x;

    const __half* Abase = A + (size_t)(bm * 256) * K;
    const __half* Bbase = BT + (size_t)(bn * 128) * K;
    const int ntiles = K >> 6;                      // 64 k per chunk

    // per-lane ldmatrix row/unit decomposition
    const int laneA_r = wy * 64 + ((lane >> 3) & 1) * 8 + (lane & 7);
    const int laneA_u = lane >> 4;
    const int laneA_s7 = laneA_r & 7;
    const int laneB_r = wx * 64 + (lane >> 4) * 8 + (lane & 7);
    const int laneB_u = (lane >> 3) & 1;
    const int laneB_s7 = laneB_r & 7;

    float acc[4][8][4];
    #pragma unroll
    for (int mt = 0; mt < 4; mt++)
        #pragma unroll
        for (int nt = 0; nt < 8; nt++)
            #pragma unroll
            for (int r = 0; r < 4; r++) acc[mt][nt][r] = 0.f;

    auto load_chunk = [&](int c) {
        const uint32_t so = smem0 + (uint32_t)(c % NSTAGE) * STAGE_BYTES;
        const int k0 = c << 6;
        #pragma unroll
        for (int t = 0; t < 8; t++) {
            const int i = tid + t * 256;
            const int r = i >> 3, u = i & 7;
            const uint32_t du = (uint32_t)((u ^ (r & 7)) << 4);
            cp_async16(so + (uint32_t)(r * 128) + du,
                       Abase + (size_t)r * K + k0 + u * 8);
        }
        #pragma unroll
        for (int t = 0; t < 4; t++) {
            const int i = tid + t * 256;
            const int r = i >> 3, u = i & 7;
            const uint32_t du = (uint32_t)((u ^ (r & 7)) << 4);
            cp_async16(so + A_STAGE_BYTES + (uint32_t)(r * 128) + du,
                       Bbase + (size_t)r * K + k0 + u * 8);
        }
        CP_COMMIT();
    };

    load_chunk(0);
    load_chunk(1);
    load_chunk(2);

    uint32_t aF[2][4][4];
    uint32_t bF[2][4][4];

    auto load_frags = [&](uint32_t sA, uint32_t sB, int ks, int buf) {
        const uint32_t uA = (uint32_t)(((ks * 2 + laneA_u) ^ laneA_s7) << 4);
        #pragma unroll
        for (int mt = 0; mt < 4; mt++)
            ldsm_x4(aF[buf][mt],
                    sA + (uint32_t)((laneA_r + mt * 16) * 128) + uA);
        const uint32_t uB = (uint32_t)(((ks * 2 + laneB_u) ^ laneB_s7) << 4);
        #pragma unroll
        for (int p = 0; p < 4; p++)
            ldsm_x4(bF[buf][p],
                    sB + (uint32_t)((laneB_r + p * 16) * 128) + uB);
    };

    for (int c = 0; c < ntiles; c++) {
        asm volatile("cp.async.wait_group 2;" ::: "memory");
        __syncthreads();

        const uint32_t sA = smem0 + (uint32_t)(c % NSTAGE) * STAGE_BYTES;
        const uint32_t sB = sA + A_STAGE_BYTES;

        load_frags(sA, sB, 0, 0);

        if (c + 3 < ntiles) load_chunk(c + 3);
        else CP_COMMIT();

        #pragma unroll
        for (int ks = 0; ks < 4; ks++) {
            const int cb = ks & 1;
            if (ks < 3) load_frags(sA, sB, ks + 1, cb ^ 1);
            #pragma unroll
            for (int p = 0; p < 4; p++) {
                #pragma unroll
                for (int mt = 0; mt < 4; mt++) {
                    mma_f16(acc[mt][2 * p],     aF[cb][mt], &bF[cb][p][0], &bF[cb][p][1]);
                    mma_f16(acc[mt][2 * p + 1], aF[cb][mt], &bF[cb][p][2], &bF[cb][p][3]);
                }
            }
        }
        __syncthreads();
    }

    // epilogue
    if (EP == 3) {
        // kv projection: +bias, then softmax over the warp's 64-col chunk
        // (one attention head) for the k half (bn < 8).
        const bool do_soft = (bn < 8);
        #pragma unroll
        for (int mt = 0; mt < 4; mt++) {
            const int r0 = bm * 256 + wy * 64 + mt * 16 + gid;
            float m01 = -1e30f, m23 = -1e30f;
            #pragma unroll
            for (int nt = 0; nt < 8; nt++) {
                const int col = bn * 128 + wx * 64 + nt * 8 + tig * 2;
                float2 b2 = *(const float2*)(bias + col);
                acc[mt][nt][0] += b2.x; acc[mt][nt][1] += b2.y;
                acc[mt][nt][2] += b2.x; acc[mt][nt][3] += b2.y;
                m01 = fmaxf(m01, fmaxf(acc[mt][nt][0], acc[mt][nt][1]));
                m23 = fmaxf(m23, fmaxf(acc[mt][nt][2], acc[mt][nt][3]));
            }
            if (do_soft) {
                m01 = fmaxf(m01, __shfl_xor_sync(0xffffffffu, m01, 1));
                m01 = fmaxf(m01, __shfl_xor_sync(0xffffffffu, m01, 2));
                m23 = fmaxf(m23, __shfl_xor_sync(0xffffffffu, m23, 1));
                m23 = fmaxf(m23, __shfl_xor_sync(0xffffffffu, m23, 2));
                float s01 = 0.f, s23 = 0.f;
                #pragma unroll
                for (int nt = 0; nt < 8; nt++) {
                    acc[mt][nt][0] = __expf(acc[mt][nt][0] - m01);
                    acc[mt][nt][1] = __expf(acc[mt][nt][1] - m01);
                    acc[mt][nt][2] = __expf(acc[mt][nt][2] - m23);
                    acc[mt][nt][3] = __expf(acc[mt][nt][3] - m23);
                    s01 += acc[mt][nt][0] + acc[mt][nt][1];
                    s23 += acc[mt][nt][2] + acc[mt][nt][3];
                }
                s01 += __shfl_xor_sync(0xffffffffu, s01, 1);
                s01 += __shfl_xor_sync(0xffffffffu, s01, 2);
                s23 += __shfl_xor_sync(0xffffffffu, s23, 1);
                s23 += __shfl_xor_sync(0xffffffffu, s23, 2);
                const float i01 = 1.f / s01, i23 = 1.f / s23;
                #pragma unroll
                for (int nt = 0; nt < 8; nt++) {
                    acc[mt][nt][0] *= i01; acc[mt][nt][1] *= i01;
                    acc[mt][nt][2] *= i23; acc[mt][nt][3] *= i23;
                }
            }
            #pragma unroll
            for (int nt = 0; nt < 8; nt++) {
                const int col = bn * 128 + wx * 64 + nt * 8 + tig * 2;
                *(float2*)(C + (size_t)r0 * Ncols + col) =
                    make_float2(acc[mt][nt][0], acc[mt][nt][1]);
                *(float2*)(C + (size_t)(r0 + 8) * Ncols + col) =
                    make_float2(acc[mt][nt][2], acc[mt][nt][3]);
            }
        }
    } else {
        #pragma unroll
        for (int mt = 0; mt < 4; mt++) {
            const int r0 = bm * 256 + wy * 64 + mt * 16 + gid;
            #pragma unroll
            for (int nt = 0; nt < 8; nt++) {
                const int col = bn * 128 + wx * 64 + nt * 8 + tig * 2;
                float2 b2 = *(const float2*)(bias + col);
                float v0 = acc[mt][nt][0] + b2.x;
                float v1 = acc[mt][nt][1] + b2.y;
                float v2 = acc[mt][nt][2] + b2.x;
                float v3 = acc[mt][nt][3] + b2.y;
                if (EP == 1) {
                    float2 ra = *(const float2*)(res + (size_t)r0 * Ncols + col);
                    float2 rb = *(const float2*)(res + (size_t)(r0 + 8) * Ncols + col);
                    v0 += ra.x; v1 += ra.y; v2 += rb.x; v3 += rb.y;
                }
                if (EP == 2) {
                    v0 = v0 * (1.f / (1.f + __expf(-v0)));
                    v1 = v1 * (1.f / (1.f + __expf(-v1)));
                    v2 = v2 * (1.f / (1.f + __expf(-v2)));
                    v3 = v3 * (1.f / (1.f + __expf(-v3)));
                    *(__half2*)(Ch + (size_t)r0 * Ncols + col) =
                        __floats2half2_rn(v0, v1);
                    *(__half2*)(Ch + (size_t)(r0 + 8) * Ncols + col) =
                        __floats2half2_rn(v2, v3);
                } else {
                    *(float2*)(C + (size_t)r0 * Ncols + col)       = make_float2(v0, v1);
                    *(float2*)(C + (size_t)(r0 + 8) * Ncols + col) = make_float2(v2, v3);
                }
            }
        }
    }
}

// ---------------------------------------------------------------------------
// Weight transpose: in[K][N] fp32 -> out[N][K] fp16
// ---------------------------------------------------------------------------
__global__ void transpose_h(const float* __restrict__ in, __half* __restrict__ out,
                            int K, int N) {
    __shared__ float t[32][33];
    const int bx = blockIdx.x * 32;  // n
    const int by = blockIdx.y * 32;  // k
    const int x = threadIdx.x, y = threadIdx.y;
    #pragma unroll
    for (int i = 0; i < 32; i += 8)
        t[y + i][x] = in[(size_t)(by + y + i) * N + bx + x];
    __syncthreads();
    #pragma unroll
    for (int i = 0; i < 32; i += 8)
        out[(size_t)(bx + y + i) * K + by + x] = __float2half_rn(t[x][y + i]);
}

// ---------------------------------------------------------------------------
// LayerNorm: fp32 in -> fp16 out (feeds GEMMs only)
// ---------------------------------------------------------------------------
__global__ void ln_kernel(const float* __restrict__ x, const float* __restrict__ g,
                          const float* __restrict__ bta, __half* __restrict__ y) {
    const int tid = threadIdx.x;
    const size_t row = blockIdx.x;
    float4 v = ((const float4*)(x + row * DD))[tid];
    __shared__ float red[32];

    float s = v.x + v.y + v.z + v.w;
    #pragma unroll
    for (int o = 16; o; o >>= 1) s += __shfl_xor_sync(0xffffffffu, s, o);
    if ((tid & 31) == 0) red[tid >> 5] = s;
    __syncthreads();
    if (tid < 32) {
        float t = (tid < 8) ? red[tid] : 0.f;
        #pragma unroll
        for (int o = 4; o; o >>= 1) t += __shfl_xor_sync(0xffffffffu, t, o);
        if (tid == 0) red[0] = t;
    }
    __syncthreads();
    const float mean = red[0] * (1.f / DD);

    float dx = v.x - mean, dy = v.y - mean, dz = v.z - mean, dw = v.w - mean;
    float ss = dx * dx + dy * dy + dz * dz + dw * dw;
    #pragma unroll
    for (int o = 16; o; o >>= 1) ss += __shfl_xor_sync(0xffffffffu, ss, o);
    __syncthreads();
    if ((tid & 31) == 0) red[tid >> 5] = ss;
    __syncthreads();
    if (tid < 32) {
        float t = (tid < 8) ? red[tid] : 0.f;
        #pragma unroll
        for (int o = 4; o; o >>= 1) t += __shfl_xor_sync(0xffffffffu, t, o);
        if (tid == 0) red[0] = t;
    }
    __syncthreads();
    const float rstd = rsqrtf(red[0] * (1.f / DD) + EPS_F);

    float4 gg = ((const float4*)g)[tid];
    float4 bb = ((const float4*)bta)[tid];
    __half2* yp = (__half2*)(y + row * DD);
    yp[2 * tid]     = __floats2half2_rn(dx * rstd * gg.x + bb.x,
                                        dy * rstd * gg.y + bb.y);
    yp[2 * tid + 1] = __floats2half2_rn(dz * rstd * gg.z + bb.z,
                                        dw * rstd * gg.w + bb.w);
}

// ---------------------------------------------------------------------------
// softmax stats over N axis of q[B,N,D] per (b, channel): writes M and 1/S
// ---------------------------------------------------------------------------
__global__ void softmax_q_stats(const float* __restrict__ q,
                                float* __restrict__ qM, float* __restrict__ qS) {
    const int b = blockIdx.y;
    const int c = (blockIdx.x << 5) + threadIdx.x;
    const int ty = threadIdx.y;
    const float* base = q + (size_t)b * NN_ * DD + c;

    float m = -1e30f, s = 0.f;
    for (int n = ty; n < NN_; n += 8) {
        float v = base[(size_t)n * DD];
        if (v > m) { s = s * __expf(m - v) + 1.f; m = v; }
        else       { s += __expf(v - m); }
    }
    __shared__ float sm[8][32], ssum[8][32];
    sm[ty][threadIdx.x] = m; ssum[ty][threadIdx.x] = s;
    __syncthreads();
    if (ty == 0) {
        float Mv = -1e30f;
        #pragma unroll
        for (int i = 0; i < 8; i++) Mv = fmaxf(Mv, sm[i][threadIdx.x]);
        float Sv = 0.f;
        #pragma unroll
        for (int i = 0; i < 8; i++)
            Sv += ssum[i][threadIdx.x] * __expf(sm[i][threadIdx.x] - Mv);
        qM[b * DD + c] = Mv;
        qS[b * DD + c] = 1.f / Sv;
    }
}

// context[b,h,:,:] = SCALE * k^T v  (64x64 per head); kv already softmaxed (k half)
__global__ void context_kernel(const float* __restrict__ kv, float* __restrict__ ctx) {
    const int bh = blockIdx.x;
    const int b = bh >> 4, h = bh & 15;
    __shared__ float Ks[64][64];
    __shared__ float Vs[64][64];
    const int tid = threadIdx.x;
    const int tx = tid & 15, ty = tid >> 4;
    const float* kvb = kv + (size_t)b * MM_ * 2048 + h * 64;

    float acc[4][4];
    #pragma unroll
    for (int i = 0; i < 4; i++)
        #pragma unroll
        for (int j = 0; j < 4; j++) acc[i][j] = 0.f;

    for (int m0 = 0; m0 < MM_; m0 += 64) {
        for (int i = tid; i < 1024; i += 256) {
            int r = i >> 4, c4 = (i & 15) << 2;
            const float* rp = kvb + (size_t)(m0 + r) * 2048 + c4;
            *(float4*)&Ks[r][c4] = *(const float4*)rp;
            *(float4*)&Vs[r][c4] = *(const float4*)(rp + 1024);
        }
        __syncthreads();
        #pragma unroll 8
        for (int mm = 0; mm < 64; mm++) {
            float a0 = Ks[mm][ty * 4 + 0], a1 = Ks[mm][ty * 4 + 1];
            float a2 = Ks[mm][ty * 4 + 2], a3 = Ks[mm][ty * 4 + 3];
            float b0 = Vs[mm][tx * 4 + 0], b1 = Vs[mm][tx * 4 + 1];
            float b2 = Vs[mm][tx * 4 + 2], b3 = Vs[mm][tx * 4 + 3];
            acc[0][0] += a0 * b0; acc[0][1] += a0 * b1; acc[0][2] += a0 * b2; acc[0][3] += a0 * b3;
            acc[1][0] += a1 * b0; acc[1][1] += a1 * b1; acc[1][2] += a1 * b2; acc[1][3] += a1 * b3;
            acc[2][0] += a2 * b0; acc[2][1] += a2 * b1; acc[2][2] += a2 * b2; acc[2][3] += a2 * b3;
            acc[3][0] += a3 * b0; acc[3][1] += a3 * b1; acc[3][2] += a3 * b2; acc[3][3] += a3 * b3;
        }
        __syncthreads();
    }
    float* cb = ctx + (size_t)bh * 64 * 64;
    #pragma unroll
    for (int i = 0; i < 4; i++) {
        float o[4];
        #pragma unroll
        for (int j = 0; j < 4; j++) o[j] = acc[i][j] * SCALE_F;
        *(float4*)(cb + (ty * 4 + i) * 64 + tx * 4) = *(float4*)&o[0];
    }
}

// out[b,n,h*64+e] = sum_d softmax_q(q)[b,n,h*64+d] * ctx[b,h,d,e]
// boff = batch offset for M-group pipelining
__global__ void apply_ctx_kernel(const float* __restrict__ q,
                                 const float* __restrict__ qM,
                                 const float* __restrict__ qS,
                                 const float* __restrict__ ctx,
                                 __half* __restrict__ outp, int boff) {
    const int bh = blockIdx.y + boff * HH;
    const int b = bh >> 4, h = bh & 15;
    const int n0 = blockIdx.x << 6;
    __shared__ float Cs[64][64];
    __shared__ float Qs[64][64];
    __shared__ float sM[64], sS[64];
    const int tid = threadIdx.x;
    const float* qb = q + ((size_t)(b * NN_ + n0)) * DD + h * 64;
    const float* cb = ctx + (size_t)bh * 64 * 64;

    if (tid < 64) {
        sM[tid] = qM[b * DD + h * 64 + tid];
        sS[tid] = qS[b * DD + h * 64 + tid];
    }
    __syncthreads();

    for (int i = tid; i < 1024; i += 256) {
        int r = i >> 4, c4 = (i & 15) << 2;
        *(float4*)&Cs[r][c4] = *(const float4*)(cb + r * 64 + c4);
        float4 qa = *(const float4*)(qb + (size_t)r * DD + c4);
        qa.x = __expf(qa.x - sM[c4 + 0]) * sS[c4 + 0];
        qa.y = __expf(qa.y - sM[c4 + 1]) * sS[c4 + 1];
        qa.z = __expf(qa.z - sM[c4 + 2]) * sS[c4 + 2];
        qa.w = __expf(qa.w - sM[c4 + 3]) * sS[c4 + 3];
        *(float4*)&Qs[r][c4] = qa;
    }
    __syncthreads();

    const int tx = tid & 15, ty = tid >> 4;
    float acc[4][4];
    #pragma unroll
    for (int i = 0; i < 4; i++)
        #pragma unroll
        for (int j = 0; j < 4; j++) acc[i][j] = 0.f;

    #pragma unroll 8
    for (int d = 0; d < 64; d++) {
        float a0 = Qs[ty * 4 + 0][d], a1 = Qs[ty * 4 + 1][d];
        float a2 = Qs[ty * 4 + 2][d], a3 = Qs[ty * 4 + 3][d];
        float b0 = Cs[d][tx * 4 + 0], b1 = Cs[d][tx * 4 + 1];
        float b2 = Cs[d][tx * 4 + 2], b3 = Cs[d][tx * 4 + 3];
        acc[0][0] += a0 * b0; acc[0][1] += a0 * b1; acc[0][2] += a0 * b2; acc[0][3] += a0 * b3;
        acc[1][0] += a1 * b0; acc[1][1] += a1 * b1; acc[1][2] += a1 * b2; acc[1][3] += a1 * b3;
        acc[2][0] += a2 * b0; acc[2][1] += a2 * b1; acc[2][2] += a2 * b2; acc[2][3] += a2 * b3;
        acc[3][0] += a3 * b0; acc[3][1] += a3 * b1; acc[3][2] += a3 * b2; acc[3][3] += a3 * b3;
    }
    __half* ob = outp + ((size_t)(b * NN_ + n0)) * DD + h * 64;
    #pragma unroll
    for (int i = 0; i < 4; i++) {
        __half2 h01 = __floats2half2_rn(acc[i][0], acc[i][1]);
        __half2 h23 = __floats2half2_rn(acc[i][2], acc[i][3]);
        __half2* op = (__half2*)(ob + (size_t)(ty * 4 + i) * DD + tx * 4);
        op[0] = h01;
        op[1] = h23;
    }
}

// ---------------------------------------------------------------------------
// Launch sequence: multi-stream fork/join DAG with M-group pipelining
// ---------------------------------------------------------------------------
extern "C" void kernel_launch(void* const* d_in, const int* in_sizes, int n_in,
                              void* d_out, int out_size) {
    (void)in_sizes; (void)n_in; (void)out_size;
    const float* x      = (const float*)d_in[0];
    const float* wt     = (const float*)d_in[1];
    const float* ln_q_g = (const float*)d_in[2];
    const float* ln_q_b = (const float*)d_in[3];
    const float* Wq     = (const float*)d_in[4];
    const float* bq     = (const float*)d_in[5];
    const float* ln_kv_g= (const float*)d_in[6];
    const float* ln_kv_b= (const float*)d_in[7];
    const float* Wkv    = (const float*)d_in[8];
    const float* bkv    = (const float*)d_in[9];
    const float* Wo     = (const float*)d_in[10];
    const float* bo     = (const float*)d_in[11];
    const float* ln_f_g = (const float*)d_in[12];
    const float* ln_f_b = (const float*)d_in[13];
    const float* W1     = (const float*)d_in[14];
    const float* b1     = (const float*)d_in[15];
    const float* W2     = (const float*)d_in[16];
    const float* b2     = (const float*)d_in[17];
    float* out = (float*)d_out;

    __half *bufA, *buf1, *WqT, *WkvT, *WoT, *W1T, *W2T;
    float *buf2, *buf3, *kv, *ctx, *qM, *qS;
    cudaGetSymbolAddress((void**)&bufA, g_bufA);
    cudaGetSymbolAddress((void**)&buf1, g_buf1);
    cudaGetSymbolAddress((void**)&buf2, g_buf2);
    cudaGetSymbolAddress((void**)&buf3, g_buf3);
    cudaGetSymbolAddress((void**)&kv,   g_kv);
    cudaGetSymbolAddress((void**)&ctx,  g_ctx);
    cudaGetSymbolAddress((void**)&qM,   g_qM);
    cudaGetSymbolAddress((void**)&qS,   g_qS);
    cudaGetSymbolAddress((void**)&WqT,  g_WqT);
    cudaGetSymbolAddress((void**)&WkvT, g_WkvT);
    cudaGetSymbolAddress((void**)&WoT,  g_WoT);
    cudaGetSymbolAddress((void**)&W1T,  g_W1T);
    cudaGetSymbolAddress((void**)&W2T,  g_W2T);

    cudaFuncSetAttribute(hgemm<0>, cudaFuncAttributeMaxDynamicSharedMemorySize, DSMEM_BYTES);
    cudaFuncSetAttribute(hgemm<1>, cudaFuncAttributeMaxDynamicSharedMemorySize, DSMEM_BYTES);
    cudaFuncSetAttribute(hgemm<2>, cudaFuncAttributeMaxDynamicSharedMemorySize, DSMEM_BYTES);
    cudaFuncSetAttribute(hgemm<3>, cudaFuncAttributeMaxDynamicSharedMemorySize, DSMEM_BYTES);

    // one-time host objects (no device memory; same captured work every call)
    static cudaStream_t sW = nullptr, sB = nullptr;
    static cudaEvent_t evRoot, evWq, evWkv, evWo, evW1, evW2, evKv, evStats, evDone;
    if (sW == nullptr) {
        cudaStreamCreateWithFlags(&sW, cudaStreamNonBlocking);
        cudaStreamCreateWithFlags(&sB, cudaStreamNonBlocking);
        cudaEventCreateWithFlags(&evRoot,  cudaEventDisableTiming);
        cudaEventCreateWithFlags(&evWq,    cudaEventDisableTiming);
        cudaEventCreateWithFlags(&evWkv,   cudaEventDisableTiming);
        cudaEventCreateWithFlags(&evWo,    cudaEventDisableTiming);
        cudaEventCreateWithFlags(&evW1,    cudaEventDisableTiming);
        cudaEventCreateWithFlags(&evW2,    cudaEventDisableTiming);
        cudaEventCreateWithFlags(&evKv,    cudaEventDisableTiming);
        cudaEventCreateWithFlags(&evStats, cudaEventDisableTiming);
        cudaEventCreateWithFlags(&evDone,  cudaEventDisableTiming);
    }

    // fork
    cudaEventRecord(evRoot, 0);
    cudaStreamWaitEvent(sW, evRoot, 0);
    cudaStreamWaitEvent(sB, evRoot, 0);

    // stream W: weight transposes
    transpose_h<<<dim3(1024 / 32, 1024 / 32), dim3(32, 8), 0, sW>>>(Wq, WqT, 1024, 1024);
    cudaEventRecord(evWq, sW);
    transpose_h<<<dim3(2048 / 32, 1024 / 32), dim3(32, 8), 0, sW>>>(Wkv, WkvT, 1024, 2048);
    cudaEventRecord(evWkv, sW);
    transpose_h<<<dim3(1024 / 32, 1024 / 32), dim3(32, 8), 0, sW>>>(Wo, WoT, 1024, 1024);
    cudaEventRecord(evWo, sW);
    transpose_h<<<dim3(4096 / 32, 1024 / 32), dim3(32, 8), 0, sW>>>(W1, W1T, 1024, 4096);
    cudaEventRecord(evW1, sW);
    transpose_h<<<dim3(1024 / 32, 4096 / 32), dim3(32, 8), 0, sW>>>(W2, W2T, 4096, 1024);
    cudaEventRecord(evW2, sW);

    // stream B: kv chain (LN(w) -> kv GEMM w/ fused softmax_k -> context)
    ln_kernel<<<ROWS_W, 256, 0, sB>>>(wt, ln_kv_g, ln_kv_b, bufA);
    cudaStreamWaitEvent(sB, evWkv, 0);
    hgemm<3><<<dim3(2048 / 128, ROWS_W / 256), 256, DSMEM_BYTES, sB>>>(
        bufA, WkvT, bkv, nullptr, kv, nullptr, 2048, DD);
    context_kernel<<<BB * HH, 256, 0, sB>>>(kv, ctx);
    cudaEventRecord(evKv, sB);

    // stream 0: q chain (full rows)
    ln_kernel<<<ROWS_X, 256>>>(x, ln_q_g, ln_q_b, buf1);
    cudaStreamWaitEvent(0, evWq, 0);
    hgemm<0><<<dim3(DD / 128, ROWS_X / 256), 256, DSMEM_BYTES>>>(
        buf1, WqT, bq, nullptr, buf2, nullptr, DD, DD);
    softmax_q_stats<<<dim3(DD / 32, BB), dim3(32, 8)>>>(buf2, qM, qS);
    cudaEventRecord(evStats, 0);

    // ---- M-group pipelined chains: g0 on stream 0, g1 on stream sB ----
    const size_t gr = GROUP_ROWS;             // 16384 rows per group
    const dim3 gGemmO(DD / 128, GROUP_ROWS / 256);
    const dim3 gGemm1(4096 / 128, GROUP_ROWS / 256);

    // chain g0 (rows [0, 16384), batches 0-3) on stream 0
    cudaStreamWaitEvent(0, evKv, 0);
    apply_ctx_kernel<<<dim3(NN_ / 64, (BB / 2) * HH), 256>>>(buf2, qM, qS, ctx, buf1, 0);
    cudaStreamWaitEvent(0, evWo, 0);
    hgemm<1><<<gGemmO, 256, DSMEM_BYTES>>>(buf1, WoT, bo, x, buf3, nullptr, DD, DD);
    ln_kernel<<<GROUP_ROWS, 256>>>(buf3, ln_f_g, ln_f_b, buf1);
    cudaStreamWaitEvent(0, evW1, 0);
    hgemm<2><<<gGemm1, 256, DSMEM_BYTES>>>(buf1, W1T, b1, nullptr, nullptr, bufA, 4096, DD);
    cudaStreamWaitEvent(0, evW2, 0);
    hgemm<1><<<gGemmO, 256, DSMEM_BYTES>>>(bufA, W2T, b2, buf3, out, nullptr, DD, 4096);

    // chain g1 (rows [16384, 32768), batches 4-7) on stream sB
    cudaStreamWaitEvent(sB, evStats, 0);
    apply_ctx_kernel<<<dim3(NN_ / 64, (BB / 2) * HH), 256, 0, sB>>>(buf2, qM, qS, ctx, buf1, BB / 2);
    cudaStreamWaitEvent(sB, evWo, 0);
    hgemm<1><<<gGemmO, 256, DSMEM_BYTES, sB>>>(buf1 + gr * DD, WoT, bo, x + gr * DD,
                                               buf3 + gr * DD, nullptr, DD, DD);
    ln_kernel<<<GROUP_ROWS, 256, 0, sB>>>(buf3 + gr * DD, ln_f_g, ln_f_b, buf1 + gr * DD);
    cudaStreamWaitEvent(sB, evW1, 0);
    hgemm<2><<<gGemm1, 256, DSMEM_BYTES, sB>>>(buf1 + gr * DD, W1T, b1, nullptr, nullptr,
                                               bufA + gr * 4096, 4096, DD);
    cudaStreamWaitEvent(sB, evW2, 0);
    hgemm<1><<<gGemmO, 256, DSMEM_BYTES, sB>>>(bufA + gr * 4096, W2T, b2, buf3 + gr * DD,
                                               out + gr * DD, nullptr, DD, 4096);
    cudaEventRecord(evDone, sB);

    // join
    cudaStreamWaitEvent(0, evDone, 0);
}